// round 8
// baseline (speedup 1.0000x reference)
#include <cuda_runtime.h>
#include <math.h>
#include <stdint.h>

// Problem constants
constexpr int Bb = 2;
constexpr int Tt = 2048;
constexpr int Cc = 1024;
constexpr int Hh = 16;
constexpr int Dd = 64;
constexpr int Mrows = Bb * Tt;        // 4096
constexpr int C3 = 3 * Cc;            // 3072
constexpr int BH = Bb * Hh;           // 32
constexpr int NQT = Tt / 128;         // 16

// Device scratch (allocation-free rule: __device__ globals)
__device__ float g_qkv[(size_t)Mrows * C3];    // [4096, 3072]
__device__ float g_attnv[(size_t)Mrows * Cc];  // [4096, 1024]
__device__ float g_tilestats[(size_t)BH * Tt * 16 * 2]; // per (row, ktile): max, expsum

// ---------------------------------------------------------------------------
// helpers
// ---------------------------------------------------------------------------
__device__ __forceinline__ uint32_t f2tf(float f) {
    uint32_t u;
    asm("cvt.rna.tf32.f32 %0, %1;" : "=r"(u) : "f"(f));
    return u;
}

__device__ __forceinline__ void mma8(float* c, const uint32_t* a, const uint32_t* b) {
    asm volatile(
        "mma.sync.aligned.m16n8k8.row.col.f32.tf32.tf32.f32 "
        "{%0,%1,%2,%3},{%4,%5,%6,%7},{%8,%9},{%0,%1,%2,%3};"
        : "+f"(c[0]), "+f"(c[1]), "+f"(c[2]), "+f"(c[3])
        : "r"(a[0]), "r"(a[1]), "r"(a[2]), "r"(a[3]), "r"(b[0]), "r"(b[1]));
}

// ---------------------------------------------------------------------------
// Dense NN GEMM: C[M,N] = A[M,K] @ B[K,N] + bias[N]  (tf32)
// Register-prefetch pipeline with convert-on-store: inner loop is pure
// LDS(u32)+MMA (no cvt in the fragment path).
// Block 128x128, BK=16, 8 warps (2m x 4n), warp tile 64x32.
// ---------------------------------------------------------------------------
__global__ __launch_bounds__(256, 2) void gemm_nn_tf32(
    const float* __restrict__ A, int lda,
    const float* __restrict__ Bm, int ldb,
    const float* __restrict__ bias,
    float* __restrict__ Cm, int ldc, int Kd)
{
    __shared__ uint32_t As[128 * 20];   // [m][k], stride 20 (pad 4)
    __shared__ uint32_t Bs[16 * 128];   // [k][n ^ ((k&3)<<3)]

    const int tid = threadIdx.x;
    const int wid = tid >> 5, lane = tid & 31;
    const int g = lane >> 2, tg = lane & 3;
    const int warp_m = wid & 1, warp_n = wid >> 1;
    const int row0 = blockIdx.y * 128;
    const int col0 = blockIdx.x * 128;

    // copy coords: A row am, 8 cols at ak; B row bk, 8 cols at bn
    const int am = tid >> 1, ak = (tid & 1) * 8;
    const int bk = tid >> 4, bn = (tid & 15) * 8;
    const int bx = bn ^ ((bk & 3) << 3);       // swizzled col base (8-aligned xor)

    const float* Ag = A + (size_t)(row0 + am) * lda + ak;
    const float* Bg = Bm + (size_t)bk * ldb + col0 + bn;
    const size_t bstep = (size_t)16 * ldb;

    float4 a0 = *(const float4*)(Ag);
    float4 a1 = *(const float4*)(Ag + 4);
    float4 b0 = *(const float4*)(Bg);
    float4 b1 = *(const float4*)(Bg + 4);

    float acc[4][4][4] = {};
    const int nIter = Kd / 16;

    for (int j = 0; j < nIter; j++) {
        // stage current regs -> smem (tf32 conversion happens HERE, once)
        {
            uint4 ua0 = {f2tf(a0.x), f2tf(a0.y), f2tf(a0.z), f2tf(a0.w)};
            uint4 ua1 = {f2tf(a1.x), f2tf(a1.y), f2tf(a1.z), f2tf(a1.w)};
            *(uint4*)&As[am * 20 + ak]     = ua0;
            *(uint4*)&As[am * 20 + ak + 4] = ua1;
            uint4 ub0 = {f2tf(b0.x), f2tf(b0.y), f2tf(b0.z), f2tf(b0.w)};
            uint4 ub1 = {f2tf(b1.x), f2tf(b1.y), f2tf(b1.z), f2tf(b1.w)};
            *(uint4*)&Bs[bk * 128 + bx]     = ub0;
            *(uint4*)&Bs[bk * 128 + bx + 4] = ub1;
        }
        __syncthreads();

        // prefetch next tile into registers (latency hides under compute)
        if (j + 1 < nIter) {
            const float* An = Ag + (j + 1) * 16;
            a0 = *(const float4*)(An);
            a1 = *(const float4*)(An + 4);
            const float* Bn = Bg + (size_t)(j + 1) * bstep;
            b0 = *(const float4*)(Bn);
            b1 = *(const float4*)(Bn + 4);
        }

#pragma unroll
        for (int ks = 0; ks < 16; ks += 8) {
            uint32_t af[4][4], bf[4][2];
#pragma unroll
            for (int mi = 0; mi < 4; mi++) {
                int m = warp_m * 64 + mi * 16;
                af[mi][0] = As[(m + g) * 20 + ks + tg];
                af[mi][1] = As[(m + g + 8) * 20 + ks + tg];
                af[mi][2] = As[(m + g) * 20 + ks + tg + 4];
                af[mi][3] = As[(m + g + 8) * 20 + ks + tg + 4];
            }
            const int xr = tg << 3;
#pragma unroll
            for (int ni = 0; ni < 4; ni++) {
                int n = warp_n * 32 + ni * 8;
                bf[ni][0] = Bs[(ks + tg) * 128 + ((n + g) ^ xr)];
                bf[ni][1] = Bs[(ks + tg + 4) * 128 + ((n + g) ^ xr)];
            }
#pragma unroll
            for (int mi = 0; mi < 4; mi++)
#pragma unroll
                for (int ni = 0; ni < 4; ni++) mma8(acc[mi][ni], af[mi], bf[ni]);
        }
        __syncthreads();
    }

#pragma unroll
    for (int mi = 0; mi < 4; mi++) {
#pragma unroll
        for (int ni = 0; ni < 4; ni++) {
            int m = row0 + warp_m * 64 + mi * 16 + g;
            int n = col0 + warp_n * 32 + ni * 8 + tg * 2;
            float2 o0 = {acc[mi][ni][0] + bias[n], acc[mi][ni][1] + bias[n + 1]};
            float2 o1 = {acc[mi][ni][2] + bias[n], acc[mi][ni][3] + bias[n + 1]};
            *(float2*)(Cm + (size_t)m * ldc + n) = o0;
            *(float2*)(Cm + (size_t)(m + 8) * ldc + n) = o1;
        }
    }
}

// ---------------------------------------------------------------------------
// Scores + per-tile softmax stats (round-4 proven version).
// Lower/diag tiles: S = scale*QK^T (diag: -inf above diagonal), write S and
// per-(row,tile) (max, expsum) stats. Upper tiles: write zeros (final output).
// ---------------------------------------------------------------------------
__global__ __launch_bounds__(256, 2) void scores_tf32(float* __restrict__ S)
{
    const int bh = blockIdx.z;
    const int q0 = blockIdx.y * 128;
    const int k0t = blockIdx.x * 128;
    float* Sb = S + (size_t)bh * Tt * Tt;
    const int tid = threadIdx.x;

    if (blockIdx.x > blockIdx.y) {
        const float4 z = {0.f, 0.f, 0.f, 0.f};
#pragma unroll
        for (int i = 0; i < 16; i++) {
            int f = i * 256 + tid;
            int r = f >> 5, c = (f & 31) * 4;
            *(float4*)(Sb + (size_t)(q0 + r) * Tt + k0t + c) = z;
        }
        return;
    }

    extern __shared__ uint32_t sm[];
    uint32_t* Qs = sm;                // [128][68]
    uint32_t* Ks = sm + 128 * 68;     // [128][68]
    __shared__ float sred[128][4];
    __shared__ float sredm[128];

    const int b = bh / Hh, h = bh % Hh;
    const int wid = tid >> 5, lane = tid & 31;
    const int g = lane >> 2, tg = lane & 3;
    const int warp_m = wid & 1, warp_n = wid >> 1;

    const float* Qb = g_qkv + (size_t)(b * Tt + q0) * C3 + h * Dd;
    const float* Kb = g_qkv + (size_t)(b * Tt + k0t) * C3 + Cc + h * Dd;

#pragma unroll
    for (int i = 0; i < 8; i++) {
        int f = tid + i * 256;
        int m = f >> 4, kq = (f & 15) * 4;
        float4 qv = *(const float4*)(Qb + (size_t)m * C3 + kq);
        Qs[m * 68 + kq + 0] = f2tf(qv.x);
        Qs[m * 68 + kq + 1] = f2tf(qv.y);
        Qs[m * 68 + kq + 2] = f2tf(qv.z);
        Qs[m * 68 + kq + 3] = f2tf(qv.w);
        float4 kv = *(const float4*)(Kb + (size_t)m * C3 + kq);
        Ks[m * 68 + kq + 0] = f2tf(kv.x);
        Ks[m * 68 + kq + 1] = f2tf(kv.y);
        Ks[m * 68 + kq + 2] = f2tf(kv.z);
        Ks[m * 68 + kq + 3] = f2tf(kv.w);
    }
    __syncthreads();

    float acc[4][4][4] = {};
#pragma unroll
    for (int ks = 0; ks < 64; ks += 8) {
        uint32_t af[4][4], bf[4][2];
#pragma unroll
        for (int mi = 0; mi < 4; mi++) {
            int m = warp_m * 64 + mi * 16;
            af[mi][0] = Qs[(m + g) * 68 + ks + tg];
            af[mi][1] = Qs[(m + g + 8) * 68 + ks + tg];
            af[mi][2] = Qs[(m + g) * 68 + ks + tg + 4];
            af[mi][3] = Qs[(m + g + 8) * 68 + ks + tg + 4];
        }
#pragma unroll
        for (int ni = 0; ni < 4; ni++) {
            int n = warp_n * 32 + ni * 8;
            bf[ni][0] = Ks[(n + g) * 68 + ks + tg];
            bf[ni][1] = Ks[(n + g) * 68 + ks + tg + 4];
        }
#pragma unroll
        for (int mi = 0; mi < 4; mi++)
#pragma unroll
            for (int ni = 0; ni < 4; ni++) mma8(acc[mi][ni], af[mi], bf[ni]);
    }

    const float scale = 0.125f;
    const bool diag = (blockIdx.x == blockIdx.y);
    const float NEG = -INFINITY;
#pragma unroll
    for (int mi = 0; mi < 4; mi++) {
        int r0 = warp_m * 64 + mi * 16 + g;
#pragma unroll
        for (int ni = 0; ni < 4; ni++) {
            int n0 = warp_n * 32 + ni * 8 + tg * 2;
            float* a = acc[mi][ni];
            a[0] *= scale; a[1] *= scale; a[2] *= scale; a[3] *= scale;
            if (diag) {
                if (n0 > r0)     a[0] = NEG;
                if (n0 + 1 > r0) a[1] = NEG;
                if (n0 > r0 + 8)     a[2] = NEG;
                if (n0 + 1 > r0 + 8) a[3] = NEG;
            }
            float2 o0 = {a[0], a[1]};
            float2 o1 = {a[2], a[3]};
            *(float2*)(Sb + (size_t)(q0 + r0) * Tt + k0t + n0) = o0;
            *(float2*)(Sb + (size_t)(q0 + r0 + 8) * Tt + k0t + n0) = o1;
        }
    }

    // ---- per-tile row stats ----
    float mx[4][2];
#pragma unroll
    for (int mi = 0; mi < 4; mi++) {
        float m0 = -INFINITY, m1 = -INFINITY;
#pragma unroll
        for (int ni = 0; ni < 4; ni++) {
            m0 = fmaxf(m0, fmaxf(acc[mi][ni][0], acc[mi][ni][1]));
            m1 = fmaxf(m1, fmaxf(acc[mi][ni][2], acc[mi][ni][3]));
        }
        m0 = fmaxf(m0, __shfl_xor_sync(0xffffffffu, m0, 1));
        m0 = fmaxf(m0, __shfl_xor_sync(0xffffffffu, m0, 2));
        m1 = fmaxf(m1, __shfl_xor_sync(0xffffffffu, m1, 1));
        m1 = fmaxf(m1, __shfl_xor_sync(0xffffffffu, m1, 2));
        mx[mi][0] = m0; mx[mi][1] = m1;
    }
    if (tg == 0) {
#pragma unroll
        for (int mi = 0; mi < 4; mi++) {
            sred[warp_m * 64 + mi * 16 + g][warp_n] = mx[mi][0];
            sred[warp_m * 64 + mi * 16 + g + 8][warp_n] = mx[mi][1];
        }
    }
    __syncthreads();
    if (tid < 128) {
        sredm[tid] = fmaxf(fmaxf(sred[tid][0], sred[tid][1]),
                           fmaxf(sred[tid][2], sred[tid][3]));
    }
    __syncthreads();
#pragma unroll
    for (int mi = 0; mi < 4; mi++) {
        float rm0 = sredm[warp_m * 64 + mi * 16 + g];
        float rm1 = sredm[warp_m * 64 + mi * 16 + g + 8];
        float s0 = 0.f, s1 = 0.f;
#pragma unroll
        for (int ni = 0; ni < 4; ni++) {
            s0 += __expf(acc[mi][ni][0] - rm0) + __expf(acc[mi][ni][1] - rm0);
            s1 += __expf(acc[mi][ni][2] - rm1) + __expf(acc[mi][ni][3] - rm1);
        }
        s0 += __shfl_xor_sync(0xffffffffu, s0, 1);
        s0 += __shfl_xor_sync(0xffffffffu, s0, 2);
        s1 += __shfl_xor_sync(0xffffffffu, s1, 1);
        s1 += __shfl_xor_sync(0xffffffffu, s1, 2);
        mx[mi][0] = s0; mx[mi][1] = s1;
    }
    __syncthreads();
    if (tg == 0) {
#pragma unroll
        for (int mi = 0; mi < 4; mi++) {
            sred[warp_m * 64 + mi * 16 + g][warp_n] = mx[mi][0];
            sred[warp_m * 64 + mi * 16 + g + 8][warp_n] = mx[mi][1];
        }
    }
    __syncthreads();
    if (tid < 128) {
        float s4 = sred[tid][0] + sred[tid][1] + sred[tid][2] + sred[tid][3];
        size_t idx = (((size_t)bh * Tt + q0 + tid) * 16 + (k0t >> 7)) * 2;
        g_tilestats[idx] = sredm[tid];
        g_tilestats[idx + 1] = s4;
    }
}

// ---------------------------------------------------------------------------
// PV with fused normalization (round-4 proven version + inline rowstats
// prologue + heavy-tiles-first). Reads raw S, p = exp(s-m)*inv, writes p in
// place (final attn_w), accumulates P@V.
// ---------------------------------------------------------------------------
__global__ __launch_bounds__(256, 2) void pv_tf32(float* __restrict__ S)
{
    __shared__ float Ps[2][128 * 20];
    __shared__ float Vs[2][16 * 64];
    __shared__ float srm[128], sri[128];

    const int qt = (NQT - 1) - blockIdx.x;     // heavy tiles first
    const int q0 = qt * 128;
    const int bh = blockIdx.y;
    const int b = bh / Hh, h = bh % Hh;
    const int tid = threadIdx.x, wid = tid >> 5, lane = tid & 31;
    const int g = lane >> 2, tg = lane & 3;
    const int warp_m = wid >> 1, warp_n = wid & 1;
    const int nkt = qt + 1;

    // prologue: combine tile stats -> per-row (max, 1/sum)
    if (tid < 128) {
        const float* st = g_tilestats + ((size_t)bh * Tt + q0 + tid) * 32;
        float m = -INFINITY;
        for (int kt = 0; kt < nkt; kt++) m = fmaxf(m, st[kt * 2]);
        float l = 0.f;
        for (int kt = 0; kt < nkt; kt++) l += st[kt * 2 + 1] * __expf(st[kt * 2] - m);
        srm[tid] = m;
        sri[tid] = 1.0f / l;
    }
    __syncthreads();

    float* Sb = S + (size_t)bh * Tt * Tt + (size_t)q0 * Tt;
    const float* Vb = g_qkv + (size_t)(b * Tt) * C3 + 2 * Cc + h * Dd;

    const int pr0 = tid >> 2, pr1 = 64 + (tid >> 2);
    const int pkq = (tid & 3) * 4;
    const float rm0 = srm[pr0], ri0 = sri[pr0];
    const float rm1 = srm[pr1], ri1 = sri[pr1];
    const int vk = tid >> 4, vnq = (tid & 15) * 4;
    const int vnx = vnq ^ ((vk & 3) << 3);

    const int nIter = nkt * 8;   // (q0+128)/16
    float4 pa, pb, vv;

    auto ldg = [&](int j) {
        const int k0 = j * 16;
        pa = *(const float4*)(Sb + (size_t)pr0 * Tt + k0 + pkq);
        pb = *(const float4*)(Sb + (size_t)pr1 * Tt + k0 + pkq);
        vv = *(const float4*)(Vb + (size_t)(k0 + vk) * C3 + vnq);
    };
    auto stage = [&](int j, int buf) {
        const int k0 = j * 16;
        float4 p0, p1;
        p0.x = __expf(pa.x - rm0) * ri0;
        p0.y = __expf(pa.y - rm0) * ri0;
        p0.z = __expf(pa.z - rm0) * ri0;
        p0.w = __expf(pa.w - rm0) * ri0;
        p1.x = __expf(pb.x - rm1) * ri1;
        p1.y = __expf(pb.y - rm1) * ri1;
        p1.z = __expf(pb.z - rm1) * ri1;
        p1.w = __expf(pb.w - rm1) * ri1;
        *(float4*)(Sb + (size_t)pr0 * Tt + k0 + pkq) = p0;   // final attn_w
        *(float4*)(Sb + (size_t)pr1 * Tt + k0 + pkq) = p1;
        float* P = Ps[buf];
        P[pr0 * 20 + pkq + 0] = p0.x; P[pr0 * 20 + pkq + 1] = p0.y;
        P[pr0 * 20 + pkq + 2] = p0.z; P[pr0 * 20 + pkq + 3] = p0.w;
        P[pr1 * 20 + pkq + 0] = p1.x; P[pr1 * 20 + pkq + 1] = p1.y;
        P[pr1 * 20 + pkq + 2] = p1.z; P[pr1 * 20 + pkq + 3] = p1.w;
        float* V = Vs[buf];
        V[vk * 64 + vnx + 0] = vv.x; V[vk * 64 + vnx + 1] = vv.y;
        V[vk * 64 + vnx + 2] = vv.z; V[vk * 64 + vnx + 3] = vv.w;
    };

    ldg(0);
    stage(0, 0);
    __syncthreads();

    float acc[2][4][4] = {};
    for (int j = 0; j < nIter; j++) {
        if (j + 1 < nIter) ldg(j + 1);
        const float* Pj = Ps[j & 1];
        const float* Vj = Vs[j & 1];
#pragma unroll
        for (int ks = 0; ks < 16; ks += 8) {
            uint32_t af[2][4], bf[4][2];
#pragma unroll
            for (int mi = 0; mi < 2; mi++) {
                int m = warp_m * 32 + mi * 16;
                af[mi][0] = f2tf(Pj[(m + g) * 20 + ks + tg]);
                af[mi][1] = f2tf(Pj[(m + g + 8) * 20 + ks + tg]);
                af[mi][2] = f2tf(Pj[(m + g) * 20 + ks + tg + 4]);
                af[mi][3] = f2tf(Pj[(m + g + 8) * 20 + ks + tg + 4]);
            }
            const int xr = tg << 3;
#pragma unroll
            for (int ni = 0; ni < 4; ni++) {
                int n = warp_n * 32 + ni * 8;
                bf[ni][0] = f2tf(Vj[(ks + tg) * 64 + ((n + g) ^ xr)]);
                bf[ni][1] = f2tf(Vj[(ks + tg + 4) * 64 + ((n + g) ^ xr)]);
            }
#pragma unroll
            for (int mi = 0; mi < 2; mi++)
#pragma unroll
                for (int ni = 0; ni < 4; ni++) mma8(acc[mi][ni], af[mi], bf[ni]);
        }
        if (j + 1 < nIter) stage(j + 1, (j + 1) & 1);
        __syncthreads();
    }

#pragma unroll
    for (int mi = 0; mi < 2; mi++) {
#pragma unroll
        for (int ni = 0; ni < 4; ni++) {
            int q = q0 + warp_m * 32 + mi * 16 + g;
            int n = warp_n * 32 + ni * 8 + tg * 2;
            float* dst0 = g_attnv + (size_t)(b * Tt + q) * Cc + h * Dd + n;
            float* dst1 = g_attnv + (size_t)(b * Tt + q + 8) * Cc + h * Dd + n;
            *(float2*)dst0 = {acc[mi][ni][0], acc[mi][ni][1]};
            *(float2*)dst1 = {acc[mi][ni][2], acc[mi][ni][3]};
        }
    }
}

// ---------------------------------------------------------------------------
extern "C" void kernel_launch(void* const* d_in, const int* in_sizes, int n_in,
                              void* d_out, int out_size)
{
    const float* x     = (const float*)d_in[0];
    const float* w_qkv = (const float*)d_in[1];
    const float* b_qkv = (const float*)d_in[2];
    const float* w_o   = (const float*)d_in[3];
    const float* b_o   = (const float*)d_in[4];

    float* out   = (float*)d_out;
    float* attnw = out + (size_t)Mrows * Cc;   // [o | attn_w]

    float* qkv_ptr   = nullptr;
    float* attnv_ptr = nullptr;
    cudaGetSymbolAddress((void**)&qkv_ptr,   g_qkv);
    cudaGetSymbolAddress((void**)&attnv_ptr, g_attnv);

    const int scores_smem = 2 * 128 * 68 * 4;   // 69632
    static bool attr_set = false;
    if (!attr_set) {
        cudaFuncSetAttribute(scores_tf32, cudaFuncAttributeMaxDynamicSharedMemorySize,
                             scores_smem);
        attr_set = true;
    }

    // 1) QKV projection
    {
        dim3 grid(C3 / 128, Mrows / 128);
        gemm_nn_tf32<<<grid, 256>>>(x, Cc, w_qkv, C3, b_qkv, qkv_ptr, C3, Cc);
    }
    // 2) Scores + tile stats (upper tiles -> zeros)
    {
        dim3 grid(Tt / 128, Tt / 128, BH);
        scores_tf32<<<grid, 256, scores_smem>>>(attnw);
    }
    // 3) P @ V with fused normalization (rowstats combined in prologue)
    {
        dim3 grid(NQT, BH);
        pv_tf32<<<grid, 256>>>(attnw);
    }
    // 4) Output projection
    {
        dim3 grid(Cc / 128, Mrows / 128);
        gemm_nn_tf32<<<grid, 256>>>(attnv_ptr, Cc, w_o, Cc, b_o, out, Cc, Cc);
    }
}

// round 10
// speedup vs baseline: 1.1792x; 1.1792x over previous
#include <cuda_runtime.h>
#include <math.h>
#include <stdint.h>

// Problem constants
constexpr int Bb = 2;
constexpr int Tt = 2048;
constexpr int Cc = 1024;
constexpr int Hh = 16;
constexpr int Dd = 64;
constexpr int Mrows = Bb * Tt;        // 4096
constexpr int C3 = 3 * Cc;            // 3072
constexpr int BH = Bb * Hh;           // 32
constexpr int NQT = Tt / 128;         // 16

// Device scratch (allocation-free rule: __device__ globals)
__device__ float g_qkv[(size_t)Mrows * C3];     // [4096, 3072]
__device__ float g_attnv[(size_t)Mrows * Cc];   // [4096, 1024] tf32-rounded
__device__ float g_xtf[(size_t)Mrows * Cc];     // x tf32-rounded
__device__ float g_wqkvT[(size_t)C3 * Cc];      // w_qkv^T, tf32-rounded
__device__ float g_woT[(size_t)Cc * Cc];        // w_o^T, tf32-rounded
__device__ float g_tilestats[(size_t)BH * Tt * 16 * 2];
__device__ float g_rowstats[(size_t)BH * Tt * 2];

// ---------------------------------------------------------------------------
// helpers
// ---------------------------------------------------------------------------
__device__ __forceinline__ uint32_t f2tf(float f) {
    uint32_t u;
    asm("cvt.rna.tf32.f32 %0, %1;" : "=r"(u) : "f"(f));
    return u;
}
__device__ __forceinline__ float f2tf_f(float f) { return __uint_as_float(f2tf(f)); }

__device__ __forceinline__ void mma8(float* c, const uint32_t* a, const uint32_t* b) {
    asm volatile(
        "mma.sync.aligned.m16n8k8.row.col.f32.tf32.tf32.f32 "
        "{%0,%1,%2,%3},{%4,%5,%6,%7},{%8,%9},{%0,%1,%2,%3};"
        : "+f"(c[0]), "+f"(c[1]), "+f"(c[2]), "+f"(c[3])
        : "r"(a[0]), "r"(a[1]), "r"(a[2]), "r"(a[3]), "r"(b[0]), "r"(b[1]));
}
__device__ __forceinline__ void ldsm4(uint32_t* r, uint32_t addr) {
    asm volatile("ldmatrix.sync.aligned.m8n8.x4.shared.b16 {%0,%1,%2,%3}, [%4];"
                 : "=r"(r[0]), "=r"(r[1]), "=r"(r[2]), "=r"(r[3]) : "r"(addr));
}
__device__ __forceinline__ void cpasync16(uint32_t saddr, const void* gptr) {
    asm volatile("cp.async.ca.shared.global [%0], [%1], 16;\n" ::"r"(saddr), "l"(gptr));
}

// ---------------------------------------------------------------------------
// Prep: tf32-round x; transpose+round weights (once, cheap).
// ---------------------------------------------------------------------------
__global__ __launch_bounds__(256) void convert_x_kernel(const float* __restrict__ x)
{
    int i = blockIdx.x * 256 + threadIdx.x;
    float4 v = *(const float4*)(x + (size_t)i * 4);
    float4 o = {f2tf_f(v.x), f2tf_f(v.y), f2tf_f(v.z), f2tf_f(v.w)};
    *(float4*)(g_xtf + (size_t)i * 4) = o;
}

// out[n][k] = round_tf32(in[k][n]); in: [K][N] row-major
__global__ __launch_bounds__(256) void transpose_tf_kernel(
    const float* __restrict__ in, float* __restrict__ out, int N, int K)
{
    __shared__ float t[32][33];
    const int tx = threadIdx.x & 31, ty = threadIdx.x >> 5;
    const int n0 = blockIdx.x * 32, k0 = blockIdx.y * 32;
#pragma unroll
    for (int j = 0; j < 4; j++) {
        int r = ty + j * 8;
        t[r][tx] = in[(size_t)(k0 + r) * N + n0 + tx];
    }
    __syncthreads();
#pragma unroll
    for (int j = 0; j < 4; j++) {
        int r = ty + j * 8;
        out[(size_t)(n0 + r) * K + k0 + tx] = f2tf_f(t[tx][r]);
    }
}

// ---------------------------------------------------------------------------
// Dense GEMM: C[M,N] = A[M,K] @ BT[N,K]^T + bias[N]  (tf32 HMMA, LDSM frags)
// A, BT pre-tf32-rounded. cp.async 3-stage, BK=16, both tiles 128x16 K-major
// stride-20 (conflict-free for LDSM). 8 warps (2m x 4n), warp tile 64x32.
// ---------------------------------------------------------------------------
__global__ __launch_bounds__(256, 2) void gemm_ldsm(
    const float* __restrict__ A, int lda,
    const float* __restrict__ BT, int ldb,
    const float* __restrict__ bias,
    float* __restrict__ Cm, int ldc, int Kd)
{
    extern __shared__ uint32_t sh[];
    constexpr int STG = 5120;            // u32/stage: As 2560 + Bs 2560

    const int tid = threadIdx.x;
    const int wid = tid >> 5, lane = tid & 31;
    const int g = lane >> 2, tg = lane & 3;
    (void)g; (void)tg;
    const int warp_m = wid & 1, warp_n = wid >> 1;
    const int row0 = blockIdx.y * 128;
    const int col0 = blockIdx.x * 128;
    const uint32_t shb = (uint32_t)__cvta_generic_to_shared(sh);

    // LDSM lane geometry
    const int arow = (lane & 7) + ((lane >> 3) & 1) * 8;   // A-matrix row order
    const int ahalf = lane >> 4;                            // col half
    const int brow = (lane & 7) + (lane >> 4) * 8;          // B pair row order
    const int bhalf = (lane >> 3) & 1;

    auto issue = [&](int kt) {
        const int s = kt % 3, k0 = kt * 16;
#pragma unroll
        for (int i = 0; i < 2; i++) {
            int c = tid + i * 256, r = c >> 2, c4 = (c & 3) * 4;
            cpasync16(shb + (s * STG + r * 20 + c4) * 4,
                      A + (size_t)(row0 + r) * lda + k0 + c4);
        }
#pragma unroll
        for (int i = 0; i < 2; i++) {
            int c = tid + i * 256, r = c >> 2, c4 = (c & 3) * 4;
            cpasync16(shb + (s * STG + 2560 + r * 20 + c4) * 4,
                      BT + (size_t)(col0 + r) * ldb + k0 + c4);
        }
        asm volatile("cp.async.commit_group;");
    };

    const int nt = Kd / 16;
    issue(0);
    issue(1);

    float acc[4][4][4] = {};

    for (int j = 0; j < nt; j++) {
        if (j == nt - 1) {
            asm volatile("cp.async.wait_group 0;");
        } else {
            asm volatile("cp.async.wait_group 1;");
        }
        __syncthreads();
        const int s = j % 3;
        const uint32_t ab = shb + (s * STG) * 4;
        const uint32_t bb = shb + (s * STG + 2560) * 4;
#pragma unroll
        for (int ks = 0; ks < 16; ks += 8) {
            uint32_t af[4][4], bf[2][4];
#pragma unroll
            for (int mi = 0; mi < 4; mi++)
                ldsm4(af[mi], ab + ((warp_m * 64 + mi * 16 + arow) * 20 + ks + ahalf * 4) * 4);
#pragma unroll
            for (int np = 0; np < 2; np++)
                ldsm4(bf[np], bb + ((warp_n * 32 + np * 16 + brow) * 20 + ks + bhalf * 4) * 4);
#pragma unroll
            for (int mi = 0; mi < 4; mi++)
#pragma unroll
                for (int np = 0; np < 2; np++) {
                    mma8(acc[mi][np * 2 + 0], af[mi], &bf[np][0]);
                    mma8(acc[mi][np * 2 + 1], af[mi], &bf[np][2]);
                }
        }
        if (j + 2 < nt) issue(j + 2);
    }

    const int g2 = lane >> 2, tg2 = lane & 3;
#pragma unroll
    for (int mi = 0; mi < 4; mi++) {
#pragma unroll
        for (int ni = 0; ni < 4; ni++) {
            int m = row0 + warp_m * 64 + mi * 16 + g2;
            int n = col0 + warp_n * 32 + ni * 8 + tg2 * 2;
            float2 o0 = {acc[mi][ni][0] + bias[n], acc[mi][ni][1] + bias[n + 1]};
            float2 o1 = {acc[mi][ni][2] + bias[n], acc[mi][ni][3] + bias[n + 1]};
            *(float2*)(Cm + (size_t)m * ldc + n) = o0;
            *(float2*)(Cm + (size_t)(m + 8) * ldc + n) = o1;
        }
    }
}

// ---------------------------------------------------------------------------
// Scores + per-tile softmax stats (round-4 math, LDSM fragment loads).
// ---------------------------------------------------------------------------
__global__ __launch_bounds__(256, 2) void scores_tf32(float* __restrict__ S)
{
    const int bh = blockIdx.z;
    const int q0 = blockIdx.y * 128;
    const int k0t = blockIdx.x * 128;
    float* Sb = S + (size_t)bh * Tt * Tt;
    const int tid = threadIdx.x;

    if (blockIdx.x > blockIdx.y) {
        const float4 z = {0.f, 0.f, 0.f, 0.f};
#pragma unroll
        for (int i = 0; i < 16; i++) {
            int f = i * 256 + tid;
            int r = f >> 5, c = (f & 31) * 4;
            *(float4*)(Sb + (size_t)(q0 + r) * Tt + k0t + c) = z;
        }
        return;
    }

    extern __shared__ uint32_t sm[];
    uint32_t* Qs = sm;                // [128][68]
    uint32_t* Ks = sm + 128 * 68;     // [128][68]
    __shared__ float sred[128][4];
    __shared__ float sredm[128];

    const int b = bh / Hh, h = bh % Hh;
    const int wid = tid >> 5, lane = tid & 31;
    const int g = lane >> 2, tg = lane & 3;
    const int warp_m = wid & 1, warp_n = wid >> 1;

    const int arow = (lane & 7) + ((lane >> 3) & 1) * 8;
    const int ahalf = lane >> 4;
    const int brow = (lane & 7) + (lane >> 4) * 8;
    const int bhalf = (lane >> 3) & 1;

    const float* Qb = g_qkv + (size_t)(b * Tt + q0) * C3 + h * Dd;
    const float* Kb = g_qkv + (size_t)(b * Tt + k0t) * C3 + Cc + h * Dd;

#pragma unroll
    for (int i = 0; i < 8; i++) {
        int f = tid + i * 256;
        int m = f >> 4, kq = (f & 15) * 4;
        float4 qv = *(const float4*)(Qb + (size_t)m * C3 + kq);
        Qs[m * 68 + kq + 0] = f2tf(qv.x);
        Qs[m * 68 + kq + 1] = f2tf(qv.y);
        Qs[m * 68 + kq + 2] = f2tf(qv.z);
        Qs[m * 68 + kq + 3] = f2tf(qv.w);
        float4 kv = *(const float4*)(Kb + (size_t)m * C3 + kq);
        Ks[m * 68 + kq + 0] = f2tf(kv.x);
        Ks[m * 68 + kq + 1] = f2tf(kv.y);
        Ks[m * 68 + kq + 2] = f2tf(kv.z);
        Ks[m * 68 + kq + 3] = f2tf(kv.w);
    }
    __syncthreads();

    const uint32_t qb = (uint32_t)__cvta_generic_to_shared(Qs);
    const uint32_t kb = (uint32_t)__cvta_generic_to_shared(Ks);

    float acc[4][4][4] = {};
#pragma unroll
    for (int ks = 0; ks < 64; ks += 8) {
        uint32_t af[4][4], bf[2][4];
#pragma unroll
        for (int mi = 0; mi < 4; mi++)
            ldsm4(af[mi], qb + ((warp_m * 64 + mi * 16 + arow) * 68 + ks + ahalf * 4) * 4);
#pragma unroll
        for (int np = 0; np < 2; np++)
            ldsm4(bf[np], kb + ((warp_n * 32 + np * 16 + brow) * 68 + ks + bhalf * 4) * 4);
#pragma unroll
        for (int mi = 0; mi < 4; mi++)
#pragma unroll
            for (int np = 0; np < 2; np++) {
                mma8(acc[mi][np * 2 + 0], af[mi], &bf[np][0]);
                mma8(acc[mi][np * 2 + 1], af[mi], &bf[np][2]);
            }
    }

    const float scale = 0.125f;
    const bool diag = (blockIdx.x == blockIdx.y);
    const float NEG = -INFINITY;
#pragma unroll
    for (int mi = 0; mi < 4; mi++) {
        int r0 = warp_m * 64 + mi * 16 + g;
#pragma unroll
        for (int ni = 0; ni < 4; ni++) {
            int n0 = warp_n * 32 + ni * 8 + tg * 2;
            float* a = acc[mi][ni];
            a[0] *= scale; a[1] *= scale; a[2] *= scale; a[3] *= scale;
            if (diag) {
                if (n0 > r0)     a[0] = NEG;
                if (n0 + 1 > r0) a[1] = NEG;
                if (n0 > r0 + 8)     a[2] = NEG;
                if (n0 + 1 > r0 + 8) a[3] = NEG;
            }
            float2 o0 = {a[0], a[1]};
            float2 o1 = {a[2], a[3]};
            *(float2*)(Sb + (size_t)(q0 + r0) * Tt + k0t + n0) = o0;
            *(float2*)(Sb + (size_t)(q0 + r0 + 8) * Tt + k0t + n0) = o1;
        }
    }

    float mx[4][2];
#pragma unroll
    for (int mi = 0; mi < 4; mi++) {
        float m0 = -INFINITY, m1 = -INFINITY;
#pragma unroll
        for (int ni = 0; ni < 4; ni++) {
            m0 = fmaxf(m0, fmaxf(acc[mi][ni][0], acc[mi][ni][1]));
            m1 = fmaxf(m1, fmaxf(acc[mi][ni][2], acc[mi][ni][3]));
        }
        m0 = fmaxf(m0, __shfl_xor_sync(0xffffffffu, m0, 1));
        m0 = fmaxf(m0, __shfl_xor_sync(0xffffffffu, m0, 2));
        m1 = fmaxf(m1, __shfl_xor_sync(0xffffffffu, m1, 1));
        m1 = fmaxf(m1, __shfl_xor_sync(0xffffffffu, m1, 2));
        mx[mi][0] = m0; mx[mi][1] = m1;
    }
    if (tg == 0) {
#pragma unroll
        for (int mi = 0; mi < 4; mi++) {
            sred[warp_m * 64 + mi * 16 + g][warp_n] = mx[mi][0];
            sred[warp_m * 64 + mi * 16 + g + 8][warp_n] = mx[mi][1];
        }
    }
    __syncthreads();
    if (tid < 128) {
        sredm[tid] = fmaxf(fmaxf(sred[tid][0], sred[tid][1]),
                           fmaxf(sred[tid][2], sred[tid][3]));
    }
    __syncthreads();
#pragma unroll
    for (int mi = 0; mi < 4; mi++) {
        float rm0 = sredm[warp_m * 64 + mi * 16 + g];
        float rm1 = sredm[warp_m * 64 + mi * 16 + g + 8];
        float s0 = 0.f, s1 = 0.f;
#pragma unroll
        for (int ni = 0; ni < 4; ni++) {
            s0 += __expf(acc[mi][ni][0] - rm0) + __expf(acc[mi][ni][1] - rm0);
            s1 += __expf(acc[mi][ni][2] - rm1) + __expf(acc[mi][ni][3] - rm1);
        }
        s0 += __shfl_xor_sync(0xffffffffu, s0, 1);
        s0 += __shfl_xor_sync(0xffffffffu, s0, 2);
        s1 += __shfl_xor_sync(0xffffffffu, s1, 1);
        s1 += __shfl_xor_sync(0xffffffffu, s1, 2);
        mx[mi][0] = s0; mx[mi][1] = s1;
    }
    __syncthreads();
    if (tg == 0) {
#pragma unroll
        for (int mi = 0; mi < 4; mi++) {
            sred[warp_m * 64 + mi * 16 + g][warp_n] = mx[mi][0];
            sred[warp_m * 64 + mi * 16 + g + 8][warp_n] = mx[mi][1];
        }
    }
    __syncthreads();
    if (tid < 128) {
        float s4 = sred[tid][0] + sred[tid][1] + sred[tid][2] + sred[tid][3];
        size_t idx = (((size_t)bh * Tt + q0 + tid) * 16 + (k0t >> 7)) * 2;
        g_tilestats[idx] = sredm[tid];
        g_tilestats[idx + 1] = s4;
    }
}

// ---------------------------------------------------------------------------
// Combine tile stats -> per-row (max, 1/sum)
// ---------------------------------------------------------------------------
__global__ __launch_bounds__(256) void rowreduce_kernel()
{
    const int r = blockIdx.x * 256 + threadIdx.x;
    const int q = r & (Tt - 1);
    const int nt = (q >> 7) + 1;
    const float* st = g_tilestats + (size_t)r * 32;
    float m = -INFINITY;
    for (int kt = 0; kt < nt; kt++) m = fmaxf(m, st[kt * 2]);
    float l = 0.f;
    for (int kt = 0; kt < nt; kt++) l += st[kt * 2 + 1] * __expf(st[kt * 2] - m);
    g_rowstats[(size_t)r * 2] = m;
    g_rowstats[(size_t)r * 2 + 1] = 1.0f / l;
}

// ---------------------------------------------------------------------------
// PV with fused normalization (round-4 structure; fragments pre-converted at
// staging and loaded via LDSM; V transposed to N-major at staging).
// attnv written tf32-rounded for the LDSM proj GEMM.
// ---------------------------------------------------------------------------
__global__ __launch_bounds__(256, 2) void pv_tf32(float* __restrict__ S)
{
    __shared__ uint32_t Ps[2][128 * 20];
    __shared__ uint32_t Vs[2][64 * 20];
    __shared__ float srm[128], sri[128];

    const int q0 = blockIdx.x * 128;
    const int bh = blockIdx.y;
    const int b = bh / Hh, h = bh % Hh;
    const int tid = threadIdx.x, wid = tid >> 5, lane = tid & 31;
    const int g = lane >> 2, tg = lane & 3;
    const int warp_m = wid >> 1, warp_n = wid & 1;

    if (tid < 128) {
        size_t rs = ((size_t)bh * Tt + q0 + tid) * 2;
        srm[tid] = g_rowstats[rs];
        sri[tid] = g_rowstats[rs + 1];
    }
    __syncthreads();

    float* Sb = S + (size_t)bh * Tt * Tt + (size_t)q0 * Tt;
    const float* Vb = g_qkv + (size_t)(b * Tt) * C3 + 2 * Cc + h * Dd;

    const int pr0 = tid >> 2, pr1 = 64 + (tid >> 2);
    const int pkq = (tid & 3) * 4;
    const float rm0 = srm[pr0], ri0 = sri[pr0];
    const float rm1 = srm[pr1], ri1 = sri[pr1];
    const int vk = tid >> 4, vnq = (tid & 15) * 4;

    const int arow = (lane & 7) + ((lane >> 3) & 1) * 8;
    const int ahalf = lane >> 4;
    const int brow = (lane & 7) + (lane >> 4) * 8;
    const int bhalf = (lane >> 3) & 1;
    const uint32_t psb = (uint32_t)__cvta_generic_to_shared(Ps);
    const uint32_t vsb = (uint32_t)__cvta_generic_to_shared(Vs);

    const int nIter = (q0 + 128) / 16;
    float4 pa, pb, vv;

    auto ldg = [&](int j) {
        const int k0 = j * 16;
        pa = *(const float4*)(Sb + (size_t)pr0 * Tt + k0 + pkq);
        pb = *(const float4*)(Sb + (size_t)pr1 * Tt + k0 + pkq);
        vv = *(const float4*)(Vb + (size_t)(k0 + vk) * C3 + vnq);
    };
    auto stage = [&](int j, int buf) {
        const int k0 = j * 16;
        float4 p0, p1;
        p0.x = __expf(pa.x - rm0) * ri0;
        p0.y = __expf(pa.y - rm0) * ri0;
        p0.z = __expf(pa.z - rm0) * ri0;
        p0.w = __expf(pa.w - rm0) * ri0;
        p1.x = __expf(pb.x - rm1) * ri1;
        p1.y = __expf(pb.y - rm1) * ri1;
        p1.z = __expf(pb.z - rm1) * ri1;
        p1.w = __expf(pb.w - rm1) * ri1;
        *(float4*)(Sb + (size_t)pr0 * Tt + k0 + pkq) = p0;   // final attn_w
        *(float4*)(Sb + (size_t)pr1 * Tt + k0 + pkq) = p1;
        uint32_t* P = Ps[buf];
        P[pr0 * 20 + pkq + 0] = f2tf(p0.x); P[pr0 * 20 + pkq + 1] = f2tf(p0.y);
        P[pr0 * 20 + pkq + 2] = f2tf(p0.z); P[pr0 * 20 + pkq + 3] = f2tf(p0.w);
        P[pr1 * 20 + pkq + 0] = f2tf(p1.x); P[pr1 * 20 + pkq + 1] = f2tf(p1.y);
        P[pr1 * 20 + pkq + 2] = f2tf(p1.z); P[pr1 * 20 + pkq + 3] = f2tf(p1.w);
        uint32_t* V = Vs[buf];                    // [n][k] stride 20
        V[(vnq + 0) * 20 + vk] = f2tf(vv.x);
        V[(vnq + 1) * 20 + vk] = f2tf(vv.y);
        V[(vnq + 2) * 20 + vk] = f2tf(vv.z);
        V[(vnq + 3) * 20 + vk] = f2tf(vv.w);
    };

    ldg(0);
    stage(0, 0);
    __syncthreads();

    float acc[2][4][4] = {};
    for (int j = 0; j < nIter; j++) {
        if (j + 1 < nIter) ldg(j + 1);
        const uint32_t pjb = psb + (uint32_t)((j & 1) * 2560 * 4);
        const uint32_t vjb = vsb + (uint32_t)((j & 1) * 1280 * 4);
#pragma unroll
        for (int ks = 0; ks < 16; ks += 8) {
            uint32_t af[2][4], bf[2][4];
#pragma unroll
            for (int mi = 0; mi < 2; mi++)
                ldsm4(af[mi], pjb + ((warp_m * 32 + mi * 16 + arow) * 20 + ks + ahalf * 4) * 4);
#pragma unroll
            for (int np = 0; np < 2; np++)
                ldsm4(bf[np], vjb + ((warp_n * 32 + np * 16 + brow) * 20 + ks + bhalf * 4) * 4);
#pragma unroll
            for (int mi = 0; mi < 2; mi++)
#pragma unroll
                for (int np = 0; np < 2; np++) {
                    mma8(acc[mi][np * 2 + 0], af[mi], &bf[np][0]);
                    mma8(acc[mi][np * 2 + 1], af[mi], &bf[np][2]);
                }
        }
        if (j + 1 < nIter) stage(j + 1, (j + 1) & 1);
        __syncthreads();
    }

#pragma unroll
    for (int mi = 0; mi < 2; mi++) {
#pragma unroll
        for (int ni = 0; ni < 4; ni++) {
            int q = q0 + warp_m * 32 + mi * 16 + g;
            int n = warp_n * 32 + ni * 8 + tg * 2;
            float* dst0 = g_attnv + (size_t)(b * Tt + q) * Cc + h * Dd + n;
            float* dst1 = g_attnv + (size_t)(b * Tt + q + 8) * Cc + h * Dd + n;
            *(float2*)dst0 = {f2tf_f(acc[mi][ni][0]), f2tf_f(acc[mi][ni][1])};
            *(float2*)dst1 = {f2tf_f(acc[mi][ni][2]), f2tf_f(acc[mi][ni][3])};
        }
    }
}

// ---------------------------------------------------------------------------
extern "C" void kernel_launch(void* const* d_in, const int* in_sizes, int n_in,
                              void* d_out, int out_size)
{
    const float* x     = (const float*)d_in[0];
    const float* w_qkv = (const float*)d_in[1];
    const float* b_qkv = (const float*)d_in[2];
    const float* w_o   = (const float*)d_in[3];
    const float* b_o   = (const float*)d_in[4];

    float* out   = (float*)d_out;
    float* attnw = out + (size_t)Mrows * Cc;   // [o | attn_w]

    float* qkv_ptr = nullptr, *attnv_ptr = nullptr, *xtf_ptr = nullptr;
    float* wqkvT_ptr = nullptr, *woT_ptr = nullptr;
    cudaGetSymbolAddress((void**)&qkv_ptr,   g_qkv);
    cudaGetSymbolAddress((void**)&attnv_ptr, g_attnv);
    cudaGetSymbolAddress((void**)&xtf_ptr,   g_xtf);
    cudaGetSymbolAddress((void**)&wqkvT_ptr, g_wqkvT);
    cudaGetSymbolAddress((void**)&woT_ptr,   g_woT);

    const int scores_smem = 2 * 128 * 68 * 4;   // 69632
    const int gemm_smem   = 3 * 5120 * 4;       // 61440
    static bool attr_set = false;
    if (!attr_set) {
        cudaFuncSetAttribute(scores_tf32, cudaFuncAttributeMaxDynamicSharedMemorySize,
                             scores_smem);
        cudaFuncSetAttribute(gemm_ldsm, cudaFuncAttributeMaxDynamicSharedMemorySize,
                             gemm_smem);
        attr_set = true;
    }

    // 0) prep
    convert_x_kernel<<<(Mrows * Cc) / 1024, 256>>>(x);
    {
        dim3 gt(C3 / 32, Cc / 32);
        transpose_tf_kernel<<<gt, 256>>>(w_qkv, wqkvT_ptr, C3, Cc);
    }
    {
        dim3 gt(Cc / 32, Cc / 32);
        transpose_tf_kernel<<<gt, 256>>>(w_o, woT_ptr, Cc, Cc);
    }
    // 1) QKV projection
    {
        dim3 grid(C3 / 128, Mrows / 128);
        gemm_ldsm<<<grid, 256, gemm_smem>>>(xtf_ptr, Cc, wqkvT_ptr, Cc, b_qkv,
                                            qkv_ptr, C3, Cc);
    }
    // 2) Scores + tile stats
    {
        dim3 grid(Tt / 128, Tt / 128, BH);
        scores_tf32<<<grid, 256, scores_smem>>>(attnw);
    }
    // 3) Row stats combine
    rowreduce_kernel<<<(BH * Tt) / 256, 256>>>();
    // 4) P @ V (fused normalization, writes final attn_w in place)
    {
        dim3 grid(NQT, BH);
        pv_tf32<<<grid, 256>>>(attnw);
    }
    // 5) Output projection
    {
        dim3 grid(Cc / 128, Mrows / 128);
        gemm_ldsm<<<grid, 256, gemm_smem>>>(attnv_ptr, Cc, woT_ptr, Cc, b_o,
                                            out, Cc, Cc);
    }
}

// round 13
// speedup vs baseline: 1.6623x; 1.4097x over previous
#include <cuda_runtime.h>
#include <cuda_fp16.h>
#include <math.h>
#include <stdint.h>

// Problem constants
constexpr int Bb = 2;
constexpr int Tt = 2048;
constexpr int Cc = 1024;
constexpr int Hh = 16;
constexpr int Dd = 64;
constexpr int Mrows = Bb * Tt;        // 4096
constexpr int C3 = 3 * Cc;            // 3072
constexpr int BH = Bb * Hh;           // 32
constexpr int NQT = Tt / 128;         // 16

// Device scratch (allocation-free rule: __device__ globals)
__device__ __half g_qkvh[(size_t)Mrows * C3];    // q,k,v fp16
__device__ __half g_attnvh[(size_t)Mrows * Cc];  // attn@V fp16
__device__ __half g_xh[(size_t)Mrows * Cc];      // x fp16
__device__ __half g_wqkvTh[(size_t)C3 * Cc];     // w_qkv^T fp16
__device__ __half g_woTh[(size_t)Cc * Cc];       // w_o^T fp16
__device__ float g_tilestats[(size_t)BH * Tt * 16 * 2];
__device__ float g_rowstats[(size_t)BH * Tt * 2];

// ---------------------------------------------------------------------------
// helpers
// ---------------------------------------------------------------------------
__device__ __forceinline__ uint32_t packh2(float a, float b) {
    __half2 h = __floats2half2_rn(a, b);
    return *(uint32_t*)&h;
}
__device__ __forceinline__ void mma16h(float* c, const uint32_t* a, const uint32_t* b) {
    asm volatile(
        "mma.sync.aligned.m16n8k16.row.col.f32.f16.f16.f32 "
        "{%0,%1,%2,%3},{%4,%5,%6,%7},{%8,%9},{%0,%1,%2,%3};"
        : "+f"(c[0]), "+f"(c[1]), "+f"(c[2]), "+f"(c[3])
        : "r"(a[0]), "r"(a[1]), "r"(a[2]), "r"(a[3]), "r"(b[0]), "r"(b[1]));
}
__device__ __forceinline__ void ldsm4(uint32_t* r, uint32_t addr) {
    asm volatile("ldmatrix.sync.aligned.m8n8.x4.shared.b16 {%0,%1,%2,%3}, [%4];"
                 : "=r"(r[0]), "=r"(r[1]), "=r"(r[2]), "=r"(r[3]) : "r"(addr));
}
__device__ __forceinline__ void ldsm4t(uint32_t* r, uint32_t addr) {
    asm volatile("ldmatrix.sync.aligned.m8n8.x4.trans.shared.b16 {%0,%1,%2,%3}, [%4];"
                 : "=r"(r[0]), "=r"(r[1]), "=r"(r[2]), "=r"(r[3]) : "r"(addr));
}
__device__ __forceinline__ void cpasync16(uint32_t saddr, const void* gptr) {
    asm volatile("cp.async.ca.shared.global [%0], [%1], 16;\n" ::"r"(saddr), "l"(gptr));
}

// ---------------------------------------------------------------------------
// Prep: x -> fp16; weights -> transposed fp16.
// ---------------------------------------------------------------------------
__global__ __launch_bounds__(256) void convert_x_h(const float* __restrict__ x)
{
    const size_t i = ((size_t)blockIdx.x * 256 + threadIdx.x) * 8;
    float4 v0 = *(const float4*)(x + i);
    float4 v1 = *(const float4*)(x + i + 4);
    uint4 o;
    o.x = packh2(v0.x, v0.y);
    o.y = packh2(v0.z, v0.w);
    o.z = packh2(v1.x, v1.y);
    o.w = packh2(v1.z, v1.w);
    *(uint4*)(g_xh + i) = o;
}

// out[n][k] = half(in[k][n]); in: [K][N] fp32 row-major
__global__ __launch_bounds__(256) void transpose_h(
    const float* __restrict__ in, __half* __restrict__ out, int N, int K)
{
    __shared__ float t[32][33];
    const int tx = threadIdx.x & 31, ty = threadIdx.x >> 5;
    const int n0 = blockIdx.x * 32, k0 = blockIdx.y * 32;
#pragma unroll
    for (int j = 0; j < 4; j++) {
        int r = ty + j * 8;
        t[r][tx] = in[(size_t)(k0 + r) * N + n0 + tx];
    }
    __syncthreads();
#pragma unroll
    for (int j = 0; j < 4; j++) {
        int r = ty + j * 8;
        out[(size_t)(n0 + r) * K + k0 + tx] = __float2half(t[tx][r]);
    }
}

// ---------------------------------------------------------------------------
// Dense GEMM: C[M,N] = A[M,K] @ BT[N,K]^T + bias[N]   (fp16 HMMA m16n8k16)
// A, BT fp16. cp.async 3-stage, BK=32 halves, tiles [128][40] halves.
// 8 warps (2m x 4n), warp tile 64x32. OUT_HALF: C fp16, else fp32.
// ---------------------------------------------------------------------------
template <bool OUT_HALF>
__global__ __launch_bounds__(256, 2) void gemm_h(
    const __half* __restrict__ A, int lda,
    const __half* __restrict__ BT, int ldb,
    const float* __restrict__ bias,
    void* __restrict__ Cv, int ldc, int Kd)
{
    extern __shared__ __half sh[];
    constexpr int STG_B = 20480;          // bytes per stage (A 10240 + B 10240)

    const int tid = threadIdx.x;
    const int wid = tid >> 5, lane = tid & 31;
    const int warp_m = wid & 1, warp_n = wid >> 1;
    const int row0 = blockIdx.y * 128;
    const int col0 = blockIdx.x * 128;
    const uint32_t shb = (uint32_t)__cvta_generic_to_shared(sh);

    const int arow = (lane & 7) + ((lane >> 3) & 1) * 8;
    const int ahalf = lane >> 4;
    const int brow = (lane & 7) + (lane >> 4) * 8;
    const int bhalf = (lane >> 3) & 1;

    auto issue = [&](int kt) {
        const int s = kt % 3, k0 = kt * 32;
#pragma unroll
        for (int i = 0; i < 2; i++) {
            int c = tid + i * 256, r = c >> 2, ch = c & 3;
            cpasync16(shb + s * STG_B + r * 80 + ch * 16,
                      A + (size_t)(row0 + r) * lda + k0 + ch * 8);
        }
#pragma unroll
        for (int i = 0; i < 2; i++) {
            int c = tid + i * 256, r = c >> 2, ch = c & 3;
            cpasync16(shb + s * STG_B + 10240 + r * 80 + ch * 16,
                      BT + (size_t)(col0 + r) * ldb + k0 + ch * 8);
        }
        asm volatile("cp.async.commit_group;");
    };

    const int nt = Kd / 32;
    issue(0);
    issue(1);

    float acc[4][4][4] = {};

    for (int j = 0; j < nt; j++) {
        if (j == nt - 1) {
            asm volatile("cp.async.wait_group 0;");
        } else {
            asm volatile("cp.async.wait_group 1;");
        }
        __syncthreads();
        const int s = j % 3;
        const uint32_t ab = shb + s * STG_B;
        const uint32_t bb = ab + 10240;
#pragma unroll
        for (int ks = 0; ks < 32; ks += 16) {
            uint32_t af[4][4], bf[2][4];
#pragma unroll
            for (int mi = 0; mi < 4; mi++)
                ldsm4(af[mi], ab + (warp_m * 64 + mi * 16 + arow) * 80 + (ks + ahalf * 8) * 2);
#pragma unroll
            for (int np = 0; np < 2; np++)
                ldsm4(bf[np], bb + (warp_n * 32 + np * 16 + brow) * 80 + (ks + bhalf * 8) * 2);
#pragma unroll
            for (int mi = 0; mi < 4; mi++)
#pragma unroll
                for (int np = 0; np < 2; np++) {
                    mma16h(acc[mi][np * 2 + 0], af[mi], &bf[np][0]);
                    mma16h(acc[mi][np * 2 + 1], af[mi], &bf[np][2]);
                }
        }
        if (j + 2 < nt) issue(j + 2);
    }

    const int g2 = lane >> 2, tg2 = lane & 3;
#pragma unroll
    for (int mi = 0; mi < 4; mi++) {
#pragma unroll
        for (int ni = 0; ni < 4; ni++) {
            int m = row0 + warp_m * 64 + mi * 16 + g2;
            int n = col0 + warp_n * 32 + ni * 8 + tg2 * 2;
            float v00 = acc[mi][ni][0] + bias[n], v01 = acc[mi][ni][1] + bias[n + 1];
            float v10 = acc[mi][ni][2] + bias[n], v11 = acc[mi][ni][3] + bias[n + 1];
            if (OUT_HALF) {
                __half* Cm = (__half*)Cv;
                uint32_t u0 = packh2(v00, v01), u1 = packh2(v10, v11);
                *(uint32_t*)(Cm + (size_t)m * ldc + n) = u0;
                *(uint32_t*)(Cm + (size_t)(m + 8) * ldc + n) = u1;
            } else {
                float* Cm = (float*)Cv;
                *(float2*)(Cm + (size_t)m * ldc + n) = {v00, v01};
                *(float2*)(Cm + (size_t)(m + 8) * ldc + n) = {v10, v11};
            }
        }
    }
}

// ---------------------------------------------------------------------------
// Scores + per-tile softmax stats (fp16 HMMA). Q,K tiles cp.async'd whole
// (128x64 halves, stride 72). Upper tiles: final zeros.
// ---------------------------------------------------------------------------
__global__ __launch_bounds__(256, 2) void scores_h(float* __restrict__ S)
{
    const int bh = blockIdx.z;
    const int q0 = blockIdx.y * 128;
    const int k0t = blockIdx.x * 128;
    float* Sb = S + (size_t)bh * Tt * Tt;
    const int tid = threadIdx.x;

    if (blockIdx.x > blockIdx.y) {
        const float4 z = {0.f, 0.f, 0.f, 0.f};
#pragma unroll
        for (int i = 0; i < 16; i++) {
            int f = i * 256 + tid;
            int r = f >> 5, c = (f & 31) * 4;
            *(float4*)(Sb + (size_t)(q0 + r) * Tt + k0t + c) = z;
        }
        return;
    }

    extern __shared__ __half smh[];
    __half* Qs = smh;                 // [128][72]
    __half* Ks = smh + 128 * 72;      // [128][72]
    __shared__ float sred[128][4];
    __shared__ float sredm[128];

    const int b = bh / Hh, h = bh % Hh;
    const int wid = tid >> 5, lane = tid & 31;
    const int g = lane >> 2, tg = lane & 3;
    const int warp_m = wid & 1, warp_n = wid >> 1;

    const int arow = (lane & 7) + ((lane >> 3) & 1) * 8;
    const int ahalf = lane >> 4;
    const int brow = (lane & 7) + (lane >> 4) * 8;
    const int bhalf = (lane >> 3) & 1;

    const __half* Qb = g_qkvh + (size_t)(b * Tt + q0) * C3 + h * Dd;
    const __half* Kb = g_qkvh + (size_t)(b * Tt + k0t) * C3 + Cc + h * Dd;
    const uint32_t qsb = (uint32_t)__cvta_generic_to_shared(Qs);
    const uint32_t ksb = (uint32_t)__cvta_generic_to_shared(Ks);

#pragma unroll
    for (int i = 0; i < 4; i++) {
        int c = tid + i * 256, r = c >> 3, ch = c & 7;
        cpasync16(qsb + r * 144 + ch * 16, Qb + (size_t)r * C3 + ch * 8);
    }
#pragma unroll
    for (int i = 0; i < 4; i++) {
        int c = tid + i * 256, r = c >> 3, ch = c & 7;
        cpasync16(ksb + r * 144 + ch * 16, Kb + (size_t)r * C3 + ch * 8);
    }
    asm volatile("cp.async.commit_group;");
    asm volatile("cp.async.wait_group 0;");
    __syncthreads();

    float acc[4][4][4] = {};
#pragma unroll
    for (int ks = 0; ks < 64; ks += 16) {
        uint32_t af[4][4], bf[2][4];
#pragma unroll
        for (int mi = 0; mi < 4; mi++)
            ldsm4(af[mi], qsb + (warp_m * 64 + mi * 16 + arow) * 144 + (ks + ahalf * 8) * 2);
#pragma unroll
        for (int np = 0; np < 2; np++)
            ldsm4(bf[np], ksb + (warp_n * 32 + np * 16 + brow) * 144 + (ks + bhalf * 8) * 2);
#pragma unroll
        for (int mi = 0; mi < 4; mi++)
#pragma unroll
            for (int np = 0; np < 2; np++) {
                mma16h(acc[mi][np * 2 + 0], af[mi], &bf[np][0]);
                mma16h(acc[mi][np * 2 + 1], af[mi], &bf[np][2]);
            }
    }

    const float scale = 0.125f;
    const bool diag = (blockIdx.x == blockIdx.y);
    const float NEG = -INFINITY;
#pragma unroll
    for (int mi = 0; mi < 4; mi++) {
        int r0 = warp_m * 64 + mi * 16 + g;
#pragma unroll
        for (int ni = 0; ni < 4; ni++) {
            int n0 = warp_n * 32 + ni * 8 + tg * 2;
            float* a = acc[mi][ni];
            a[0] *= scale; a[1] *= scale; a[2] *= scale; a[3] *= scale;
            if (diag) {
                if (n0 > r0)     a[0] = NEG;
                if (n0 + 1 > r0) a[1] = NEG;
                if (n0 > r0 + 8)     a[2] = NEG;
                if (n0 + 1 > r0 + 8) a[3] = NEG;
            }
            float2 o0 = {a[0], a[1]};
            float2 o1 = {a[2], a[3]};
            *(float2*)(Sb + (size_t)(q0 + r0) * Tt + k0t + n0) = o0;
            *(float2*)(Sb + (size_t)(q0 + r0 + 8) * Tt + k0t + n0) = o1;
        }
    }

    float mx[4][2];
#pragma unroll
    for (int mi = 0; mi < 4; mi++) {
        float m0 = -INFINITY, m1 = -INFINITY;
#pragma unroll
        for (int ni = 0; ni < 4; ni++) {
            m0 = fmaxf(m0, fmaxf(acc[mi][ni][0], acc[mi][ni][1]));
            m1 = fmaxf(m1, fmaxf(acc[mi][ni][2], acc[mi][ni][3]));
        }
        m0 = fmaxf(m0, __shfl_xor_sync(0xffffffffu, m0, 1));
        m0 = fmaxf(m0, __shfl_xor_sync(0xffffffffu, m0, 2));
        m1 = fmaxf(m1, __shfl_xor_sync(0xffffffffu, m1, 1));
        m1 = fmaxf(m1, __shfl_xor_sync(0xffffffffu, m1, 2));
        mx[mi][0] = m0; mx[mi][1] = m1;
    }
    if (tg == 0) {
#pragma unroll
        for (int mi = 0; mi < 4; mi++) {
            sred[warp_m * 64 + mi * 16 + g][warp_n] = mx[mi][0];
            sred[warp_m * 64 + mi * 16 + g + 8][warp_n] = mx[mi][1];
        }
    }
    __syncthreads();
    if (tid < 128) {
        sredm[tid] = fmaxf(fmaxf(sred[tid][0], sred[tid][1]),
                           fmaxf(sred[tid][2], sred[tid][3]));
    }
    __syncthreads();
#pragma unroll
    for (int mi = 0; mi < 4; mi++) {
        float rm0 = sredm[warp_m * 64 + mi * 16 + g];
        float rm1 = sredm[warp_m * 64 + mi * 16 + g + 8];
        float s0 = 0.f, s1 = 0.f;
#pragma unroll
        for (int ni = 0; ni < 4; ni++) {
            s0 += __expf(acc[mi][ni][0] - rm0) + __expf(acc[mi][ni][1] - rm0);
            s1 += __expf(acc[mi][ni][2] - rm1) + __expf(acc[mi][ni][3] - rm1);
        }
        s0 += __shfl_xor_sync(0xffffffffu, s0, 1);
        s0 += __shfl_xor_sync(0xffffffffu, s0, 2);
        s1 += __shfl_xor_sync(0xffffffffu, s1, 1);
        s1 += __shfl_xor_sync(0xffffffffu, s1, 2);
        mx[mi][0] = s0; mx[mi][1] = s1;
    }
    __syncthreads();
    if (tg == 0) {
#pragma unroll
        for (int mi = 0; mi < 4; mi++) {
            sred[warp_m * 64 + mi * 16 + g][warp_n] = mx[mi][0];
            sred[warp_m * 64 + mi * 16 + g + 8][warp_n] = mx[mi][1];
        }
    }
    __syncthreads();
    if (tid < 128) {
        float s4 = sred[tid][0] + sred[tid][1] + sred[tid][2] + sred[tid][3];
        size_t idx = (((size_t)bh * Tt + q0 + tid) * 16 + (k0t >> 7)) * 2;
        g_tilestats[idx] = sredm[tid];
        g_tilestats[idx + 1] = s4;
    }
}

// ---------------------------------------------------------------------------
// Combine tile stats -> per-row (max, 1/sum)
// ---------------------------------------------------------------------------
__global__ __launch_bounds__(256) void rowreduce_kernel()
{
    const int r = blockIdx.x * 256 + threadIdx.x;
    const int q = r & (Tt - 1);
    const int nt = (q >> 7) + 1;
    const float* st = g_tilestats + (size_t)r * 32;
    float m = -INFINITY;
    for (int kt = 0; kt < nt; kt++) m = fmaxf(m, st[kt * 2]);
    float l = 0.f;
    for (int kt = 0; kt < nt; kt++) l += st[kt * 2 + 1] * __expf(st[kt * 2] - m);
    g_rowstats[(size_t)r * 2] = m;
    g_rowstats[(size_t)r * 2 + 1] = 1.0f / l;
}

// ---------------------------------------------------------------------------
// PV, fused normalization. BK=32. S rows read fp32, P written fp32 in place
// (final attn_w) and staged fp16 for mma. V fp16 via cp.async, ldmatrix.trans.
// attnv written fp16. 8 warps (4m x 2n), warp tile 32x32.
// ---------------------------------------------------------------------------
__global__ __launch_bounds__(256, 2) void pv_h(float* __restrict__ S)
{
    __shared__ __half Ps[2][128 * 40];
    __shared__ __half Vs[2][32 * 72];
    __shared__ float srm[128], sri[128];

    const int q0 = blockIdx.x * 128;
    const int bh = blockIdx.y;
    const int b = bh / Hh, h = bh % Hh;
    const int tid = threadIdx.x, wid = tid >> 5, lane = tid & 31;
    const int g = lane >> 2, tg = lane & 3;
    const int warp_m = wid >> 1, warp_n = wid & 1;

    if (tid < 128) {
        size_t rs = ((size_t)bh * Tt + q0 + tid) * 2;
        srm[tid] = g_rowstats[rs];
        sri[tid] = g_rowstats[rs + 1];
    }
    __syncthreads();

    float* Sb = S + (size_t)bh * Tt * Tt + (size_t)q0 * Tt;
    const __half* Vb = g_qkvh + (size_t)(b * Tt) * C3 + 2 * Cc + h * Dd;

    const int pr0 = tid >> 2, pr1 = 64 + (tid >> 2);
    const int pc8 = (tid & 3) * 8;
    const float rm0 = srm[pr0], ri0 = sri[pr0];
    const float rm1 = srm[pr1], ri1 = sri[pr1];

    const int arow = (lane & 7) + ((lane >> 3) & 1) * 8;
    const int ahalf = lane >> 4;
    const int krow = (lane & 7) + ((lane >> 3) & 1) * 8;
    const int nhalf = (lane >> 4) * 8;
    const uint32_t psb = (uint32_t)__cvta_generic_to_shared(Ps);
    const uint32_t vsb = (uint32_t)__cvta_generic_to_shared(Vs);

    const int nIter = (q0 + 128) / 32;
    float4 pa0, pa1, pb0, pb1;

    auto issueV = [&](int j) {
        const int k0 = j * 32;
        const uint32_t vb = vsb + (uint32_t)((j & 1) * 32 * 72 * 2);
        int r = tid >> 3, ch = tid & 7;
        cpasync16(vb + r * 144 + ch * 16, Vb + (size_t)(k0 + r) * C3 + ch * 8);
        asm volatile("cp.async.commit_group;");
    };
    auto ldg = [&](int j) {
        const int k0 = j * 32;
        pa0 = *(const float4*)(Sb + (size_t)pr0 * Tt + k0 + pc8);
        pa1 = *(const float4*)(Sb + (size_t)pr0 * Tt + k0 + pc8 + 4);
        pb0 = *(const float4*)(Sb + (size_t)pr1 * Tt + k0 + pc8);
        pb1 = *(const float4*)(Sb + (size_t)pr1 * Tt + k0 + pc8 + 4);
    };
    auto stage = [&](int j, int buf) {
        const int k0 = j * 32;
        float p[16];
        p[0] = __expf(pa0.x - rm0) * ri0;  p[1] = __expf(pa0.y - rm0) * ri0;
        p[2] = __expf(pa0.z - rm0) * ri0;  p[3] = __expf(pa0.w - rm0) * ri0;
        p[4] = __expf(pa1.x - rm0) * ri0;  p[5] = __expf(pa1.y - rm0) * ri0;
        p[6] = __expf(pa1.z - rm0) * ri0;  p[7] = __expf(pa1.w - rm0) * ri0;
        p[8]  = __expf(pb0.x - rm1) * ri1; p[9]  = __expf(pb0.y - rm1) * ri1;
        p[10] = __expf(pb0.z - rm1) * ri1; p[11] = __expf(pb0.w - rm1) * ri1;
        p[12] = __expf(pb1.x - rm1) * ri1; p[13] = __expf(pb1.y - rm1) * ri1;
        p[14] = __expf(pb1.z - rm1) * ri1; p[15] = __expf(pb1.w - rm1) * ri1;
        float* d0 = Sb + (size_t)pr0 * Tt + k0 + pc8;
        float* d1 = Sb + (size_t)pr1 * Tt + k0 + pc8;
        *(float4*)(d0)     = {p[0], p[1], p[2], p[3]};
        *(float4*)(d0 + 4) = {p[4], p[5], p[6], p[7]};
        *(float4*)(d1)     = {p[8], p[9], p[10], p[11]};
        *(float4*)(d1 + 4) = {p[12], p[13], p[14], p[15]};
        __half* P = Ps[buf];
        uint4 u0 = {packh2(p[0], p[1]), packh2(p[2], p[3]),
                    packh2(p[4], p[5]), packh2(p[6], p[7])};
        uint4 u1 = {packh2(p[8], p[9]), packh2(p[10], p[11]),
                    packh2(p[12], p[13]), packh2(p[14], p[15])};
        *(uint4*)(P + pr0 * 40 + pc8) = u0;
        *(uint4*)(P + pr1 * 40 + pc8) = u1;
    };

    issueV(0);
    ldg(0);
    stage(0, 0);

    float acc[2][4][4] = {};
    for (int j = 0; j < nIter; j++) {
        if (j + 1 < nIter) {
            ldg(j + 1);
            issueV(j + 1);
            asm volatile("cp.async.wait_group 1;");
        } else {
            asm volatile("cp.async.wait_group 0;");
        }
        __syncthreads();   // V(j) + Ps(j) visible

        const uint32_t pjb = psb + (uint32_t)((j & 1) * 128 * 40 * 2);
        const uint32_t vjb = vsb + (uint32_t)((j & 1) * 32 * 72 * 2);
#pragma unroll
        for (int ks = 0; ks < 32; ks += 16) {
            uint32_t af[2][4], bf[2][4];
#pragma unroll
            for (int mi = 0; mi < 2; mi++)
                ldsm4(af[mi], pjb + (warp_m * 32 + mi * 16 + arow) * 80 + (ks + ahalf * 8) * 2);
#pragma unroll
            for (int np = 0; np < 2; np++)
                ldsm4t(bf[np], vjb + (ks + krow) * 144 + (warp_n * 32 + np * 16 + nhalf) * 2);
#pragma unroll
            for (int mi = 0; mi < 2; mi++)
#pragma unroll
                for (int np = 0; np < 2; np++) {
                    mma16h(acc[mi][np * 2 + 0], af[mi], &bf[np][0]);
                    mma16h(acc[mi][np * 2 + 1], af[mi], &bf[np][2]);
                }
        }
        if (j + 1 < nIter) stage(j + 1, (j + 1) & 1);
        __syncthreads();   // protect Ps/Vs buffers
    }

#pragma unroll
    for (int mi = 0; mi < 2; mi++) {
#pragma unroll
        for (int ni = 0; ni < 4; ni++) {
            int q = q0 + warp_m * 32 + mi * 16 + g;
            int n = warp_n * 32 + ni * 8 + tg * 2;
            __half* dst0 = g_attnvh + (size_t)(b * Tt + q) * Cc + h * Dd + n;
            __half* dst1 = g_attnvh + (size_t)(b * Tt + q + 8) * Cc + h * Dd + n;
            *(uint32_t*)dst0 = packh2(acc[mi][ni][0], acc[mi][ni][1]);
            *(uint32_t*)dst1 = packh2(acc[mi][ni][2], acc[mi][ni][3]);
        }
    }
}

// ---------------------------------------------------------------------------
extern "C" void kernel_launch(void* const* d_in, const int* in_sizes, int n_in,
                              void* d_out, int out_size)
{
    const float* x     = (const float*)d_in[0];
    const float* w_qkv = (const float*)d_in[1];
    const float* b_qkv = (const float*)d_in[2];
    const float* w_o   = (const float*)d_in[3];
    const float* b_o   = (const float*)d_in[4];

    float* out   = (float*)d_out;
    float* attnw = out + (size_t)Mrows * Cc;   // [o | attn_w]

    __half *qkvh_ptr = nullptr, *attnvh_ptr = nullptr, *xh_ptr = nullptr;
    __half *wqkvTh_ptr = nullptr, *woTh_ptr = nullptr;
    cudaGetSymbolAddress((void**)&qkvh_ptr,   g_qkvh);
    cudaGetSymbolAddress((void**)&attnvh_ptr, g_attnvh);
    cudaGetSymbolAddress((void**)&xh_ptr,     g_xh);
    cudaGetSymbolAddress((void**)&wqkvTh_ptr, g_wqkvTh);
    cudaGetSymbolAddress((void**)&woTh_ptr,   g_woTh);

    const int gemm_smem   = 3 * 20480;      // 61440
    const int scores_smem = 2 * 128 * 72 * 2;  // 36864
    static bool attr_set = false;
    if (!attr_set) {
        cudaFuncSetAttribute(gemm_h<true>, cudaFuncAttributeMaxDynamicSharedMemorySize,
                             gemm_smem);
        cudaFuncSetAttribute(gemm_h<false>, cudaFuncAttributeMaxDynamicSharedMemorySize,
                             gemm_smem);
        cudaFuncSetAttribute(scores_h, cudaFuncAttributeMaxDynamicSharedMemorySize,
                             scores_smem);
        attr_set = true;
    }

    // 0) prep: x -> fp16; weights -> transposed fp16
    convert_x_h<<<(Mrows * Cc) / (256 * 8), 256>>>(x);
    {
        dim3 gt(C3 / 32, Cc / 32);
        transpose_h<<<gt, 256>>>(w_qkv, wqkvTh_ptr, C3, Cc);
    }
    {
        dim3 gt(Cc / 32, Cc / 32);
        transpose_h<<<gt, 256>>>(w_o, woTh_ptr, Cc, Cc);
    }
    // 1) QKV projection (fp16 in/out)
    {
        dim3 grid(C3 / 128, Mrows / 128);
        gemm_h<true><<<grid, 256, gemm_smem>>>(xh_ptr, Cc, wqkvTh_ptr, Cc, b_qkv,
                                               qkvh_ptr, C3, Cc);
    }
    // 2) Scores + tile stats (upper tiles -> final zeros)
    {
        dim3 grid(Tt / 128, Tt / 128, BH);
        scores_h<<<grid, 256, scores_smem>>>(attnw);
    }
    // 3) Row stats combine
    rowreduce_kernel<<<(BH * Tt) / 256, 256>>>();
    // 4) P @ V (fused normalization, writes final attn_w in place)
    {
        dim3 grid(NQT, BH);
        pv_h<<<grid, 256>>>(attnw);
    }
    // 5) Output projection (fp16 in, fp32 out)
    {
        dim3 grid(Cc / 128, Mrows / 128);
        gemm_h<false><<<grid, 256, gemm_smem>>>(attnvh_ptr, Cc, woTh_ptr, Cc, b_o,
                                                out, Cc, Cc);
    }
}

// round 14
// speedup vs baseline: 1.7785x; 1.0699x over previous
#include <cuda_runtime.h>
#include <cuda_fp16.h>
#include <math.h>
#include <stdint.h>

// Problem constants
constexpr int Bb = 2;
constexpr int Tt = 2048;
constexpr int Cc = 1024;
constexpr int Hh = 16;
constexpr int Dd = 64;
constexpr int Mrows = Bb * Tt;        // 4096
constexpr int C3 = 3 * Cc;            // 3072
constexpr int BH = Bb * Hh;           // 32
constexpr int NQT = Tt / 128;         // 16

// Device scratch
__device__ __half g_qkvh[(size_t)Mrows * C3];    // q,k,v fp16
__device__ __half g_attnvh[(size_t)Mrows * Cc];  // attn@V fp16
__device__ __half g_xh[(size_t)Mrows * Cc];      // x fp16
__device__ __half g_wqkvTh[(size_t)C3 * Cc];     // w_qkv^T fp16
__device__ __half g_woTh[(size_t)Cc * Cc];       // w_o^T fp16
__device__ __half g_Eh[(size_t)BH * Tt * Tt];    // E = exp(s - m_tile), fp16
__device__ float g_tilestats[(size_t)BH * Tt * 16 * 2]; // (max, expsum) per (row, ktile)

// ---------------------------------------------------------------------------
// helpers
// ---------------------------------------------------------------------------
__device__ __forceinline__ uint32_t packh2(float a, float b) {
    __half2 h = __floats2half2_rn(a, b);
    return *(uint32_t*)&h;
}
__device__ __forceinline__ uint32_t hmul2u(uint32_t a, uint32_t f) {
    __half2 r = __hmul2(*(__half2*)&a, *(__half2*)&f);
    return *(uint32_t*)&r;
}
__device__ __forceinline__ void mma16h(float* c, const uint32_t* a, const uint32_t* b) {
    asm volatile(
        "mma.sync.aligned.m16n8k16.row.col.f32.f16.f16.f32 "
        "{%0,%1,%2,%3},{%4,%5,%6,%7},{%8,%9},{%0,%1,%2,%3};"
        : "+f"(c[0]), "+f"(c[1]), "+f"(c[2]), "+f"(c[3])
        : "r"(a[0]), "r"(a[1]), "r"(a[2]), "r"(a[3]), "r"(b[0]), "r"(b[1]));
}
__device__ __forceinline__ void ldsm4(uint32_t* r, uint32_t addr) {
    asm volatile("ldmatrix.sync.aligned.m8n8.x4.shared.b16 {%0,%1,%2,%3}, [%4];"
                 : "=r"(r[0]), "=r"(r[1]), "=r"(r[2]), "=r"(r[3]) : "r"(addr));
}
__device__ __forceinline__ void ldsm4t(uint32_t* r, uint32_t addr) {
    asm volatile("ldmatrix.sync.aligned.m8n8.x4.trans.shared.b16 {%0,%1,%2,%3}, [%4];"
                 : "=r"(r[0]), "=r"(r[1]), "=r"(r[2]), "=r"(r[3]) : "r"(addr));
}
__device__ __forceinline__ void cpasync16(uint32_t saddr, const void* gptr) {
    asm volatile("cp.async.ca.shared.global [%0], [%1], 16;\n" ::"r"(saddr), "l"(gptr));
}

// ---------------------------------------------------------------------------
// Prep: x -> fp16; weights -> transposed fp16.
// ---------------------------------------------------------------------------
__global__ __launch_bounds__(256) void convert_x_h(const float* __restrict__ x)
{
    const size_t i = ((size_t)blockIdx.x * 256 + threadIdx.x) * 8;
    float4 v0 = *(const float4*)(x + i);
    float4 v1 = *(const float4*)(x + i + 4);
    uint4 o;
    o.x = packh2(v0.x, v0.y);
    o.y = packh2(v0.z, v0.w);
    o.z = packh2(v1.x, v1.y);
    o.w = packh2(v1.z, v1.w);
    *(uint4*)(g_xh + i) = o;
}

__global__ __launch_bounds__(256) void transpose_h(
    const float* __restrict__ in, __half* __restrict__ out, int N, int K)
{
    __shared__ float t[32][33];
    const int tx = threadIdx.x & 31, ty = threadIdx.x >> 5;
    const int n0 = blockIdx.x * 32, k0 = blockIdx.y * 32;
#pragma unroll
    for (int j = 0; j < 4; j++) {
        int r = ty + j * 8;
        t[r][tx] = in[(size_t)(k0 + r) * N + n0 + tx];
    }
    __syncthreads();
#pragma unroll
    for (int j = 0; j < 4; j++) {
        int r = ty + j * 8;
        out[(size_t)(n0 + r) * K + k0 + tx] = __float2half(t[tx][r]);
    }
}

// ---------------------------------------------------------------------------
// Dense GEMM (fp16 HMMA m16n8k16), round-13 proven.
// ---------------------------------------------------------------------------
template <bool OUT_HALF>
__global__ __launch_bounds__(256, 2) void gemm_h(
    const __half* __restrict__ A, int lda,
    const __half* __restrict__ BT, int ldb,
    const float* __restrict__ bias,
    void* __restrict__ Cv, int ldc, int Kd)
{
    extern __shared__ __half sh[];
    constexpr int STG_B = 20480;

    const int tid = threadIdx.x;
    const int wid = tid >> 5, lane = tid & 31;
    const int warp_m = wid & 1, warp_n = wid >> 1;
    const int row0 = blockIdx.y * 128;
    const int col0 = blockIdx.x * 128;
    const uint32_t shb = (uint32_t)__cvta_generic_to_shared(sh);

    const int arow = (lane & 7) + ((lane >> 3) & 1) * 8;
    const int ahalf = lane >> 4;
    const int brow = (lane & 7) + (lane >> 4) * 8;
    const int bhalf = (lane >> 3) & 1;

    auto issue = [&](int kt) {
        const int s = kt % 3, k0 = kt * 32;
#pragma unroll
        for (int i = 0; i < 2; i++) {
            int c = tid + i * 256, r = c >> 2, ch = c & 3;
            cpasync16(shb + s * STG_B + r * 80 + ch * 16,
                      A + (size_t)(row0 + r) * lda + k0 + ch * 8);
        }
#pragma unroll
        for (int i = 0; i < 2; i++) {
            int c = tid + i * 256, r = c >> 2, ch = c & 3;
            cpasync16(shb + s * STG_B + 10240 + r * 80 + ch * 16,
                      BT + (size_t)(col0 + r) * ldb + k0 + ch * 8);
        }
        asm volatile("cp.async.commit_group;");
    };

    const int nt = Kd / 32;
    issue(0);
    issue(1);

    float acc[4][4][4] = {};

    for (int j = 0; j < nt; j++) {
        if (j == nt - 1) {
            asm volatile("cp.async.wait_group 0;");
        } else {
            asm volatile("cp.async.wait_group 1;");
        }
        __syncthreads();
        const int s = j % 3;
        const uint32_t ab = shb + s * STG_B;
        const uint32_t bb = ab + 10240;
#pragma unroll
        for (int ks = 0; ks < 32; ks += 16) {
            uint32_t af[4][4], bf[2][4];
#pragma unroll
            for (int mi = 0; mi < 4; mi++)
                ldsm4(af[mi], ab + (warp_m * 64 + mi * 16 + arow) * 80 + (ks + ahalf * 8) * 2);
#pragma unroll
            for (int np = 0; np < 2; np++)
                ldsm4(bf[np], bb + (warp_n * 32 + np * 16 + brow) * 80 + (ks + bhalf * 8) * 2);
#pragma unroll
            for (int mi = 0; mi < 4; mi++)
#pragma unroll
                for (int np = 0; np < 2; np++) {
                    mma16h(acc[mi][np * 2 + 0], af[mi], &bf[np][0]);
                    mma16h(acc[mi][np * 2 + 1], af[mi], &bf[np][2]);
                }
        }
        if (j + 2 < nt) issue(j + 2);
    }

    const int g2 = lane >> 2, tg2 = lane & 3;
#pragma unroll
    for (int mi = 0; mi < 4; mi++) {
#pragma unroll
        for (int ni = 0; ni < 4; ni++) {
            int m = row0 + warp_m * 64 + mi * 16 + g2;
            int n = col0 + warp_n * 32 + ni * 8 + tg2 * 2;
            float v00 = acc[mi][ni][0] + bias[n], v01 = acc[mi][ni][1] + bias[n + 1];
            float v10 = acc[mi][ni][2] + bias[n], v11 = acc[mi][ni][3] + bias[n + 1];
            if (OUT_HALF) {
                __half* Cm = (__half*)Cv;
                *(uint32_t*)(Cm + (size_t)m * ldc + n) = packh2(v00, v01);
                *(uint32_t*)(Cm + (size_t)(m + 8) * ldc + n) = packh2(v10, v11);
            } else {
                float* Cm = (float*)Cv;
                *(float2*)(Cm + (size_t)m * ldc + n) = {v00, v01};
                *(float2*)(Cm + (size_t)(m + 8) * ldc + n) = {v10, v11};
            }
        }
    }
}

// ---------------------------------------------------------------------------
// Scores: E = exp(scale*QK^T - tile_rowmax) -> g_Eh (fp16), stats -> gmem.
// Upper tiles: final zeros into attn_w.
// ---------------------------------------------------------------------------
__global__ __launch_bounds__(256, 2) void scores_h(float* __restrict__ S)
{
    const int bh = blockIdx.z;
    const int q0 = blockIdx.y * 128;
    const int k0t = blockIdx.x * 128;
    const int tid = threadIdx.x;

    if (blockIdx.x > blockIdx.y) {
        float* Sb = S + (size_t)bh * Tt * Tt;
        const float4 z = {0.f, 0.f, 0.f, 0.f};
#pragma unroll
        for (int i = 0; i < 16; i++) {
            int f = i * 256 + tid;
            int r = f >> 5, c = (f & 31) * 4;
            *(float4*)(Sb + (size_t)(q0 + r) * Tt + k0t + c) = z;
        }
        return;
    }

    extern __shared__ __half smh[];
    __half* Qs = smh;                 // [128][72]
    __half* Ks = smh + 128 * 72;      // [128][72]
    __shared__ float sred[128][4];
    __shared__ float sredm[128];

    const int b = bh / Hh, h = bh % Hh;
    const int wid = tid >> 5, lane = tid & 31;
    const int g = lane >> 2, tg = lane & 3;
    const int warp_m = wid & 1, warp_n = wid >> 1;

    const int arow = (lane & 7) + ((lane >> 3) & 1) * 8;
    const int ahalf = lane >> 4;
    const int brow = (lane & 7) + (lane >> 4) * 8;
    const int bhalf = (lane >> 3) & 1;

    const __half* Qb = g_qkvh + (size_t)(b * Tt + q0) * C3 + h * Dd;
    const __half* Kb = g_qkvh + (size_t)(b * Tt + k0t) * C3 + Cc + h * Dd;
    const uint32_t qsb = (uint32_t)__cvta_generic_to_shared(Qs);
    const uint32_t ksb = (uint32_t)__cvta_generic_to_shared(Ks);

#pragma unroll
    for (int i = 0; i < 4; i++) {
        int c = tid + i * 256, r = c >> 3, ch = c & 7;
        cpasync16(qsb + r * 144 + ch * 16, Qb + (size_t)r * C3 + ch * 8);
    }
#pragma unroll
    for (int i = 0; i < 4; i++) {
        int c = tid + i * 256, r = c >> 3, ch = c & 7;
        cpasync16(ksb + r * 144 + ch * 16, Kb + (size_t)r * C3 + ch * 8);
    }
    asm volatile("cp.async.commit_group;");
    asm volatile("cp.async.wait_group 0;");
    __syncthreads();

    float acc[4][4][4] = {};
#pragma unroll
    for (int ks = 0; ks < 64; ks += 16) {
        uint32_t af[4][4], bf[2][4];
#pragma unroll
        for (int mi = 0; mi < 4; mi++)
            ldsm4(af[mi], qsb + (warp_m * 64 + mi * 16 + arow) * 144 + (ks + ahalf * 8) * 2);
#pragma unroll
        for (int np = 0; np < 2; np++)
            ldsm4(bf[np], ksb + (warp_n * 32 + np * 16 + brow) * 144 + (ks + bhalf * 8) * 2);
#pragma unroll
        for (int mi = 0; mi < 4; mi++)
#pragma unroll
            for (int np = 0; np < 2; np++) {
                mma16h(acc[mi][np * 2 + 0], af[mi], &bf[np][0]);
                mma16h(acc[mi][np * 2 + 1], af[mi], &bf[np][2]);
            }
    }

    // scale + diag mask
    const float scale = 0.125f;
    const bool diag = (blockIdx.x == blockIdx.y);
    const float NEG = -INFINITY;
#pragma unroll
    for (int mi = 0; mi < 4; mi++) {
        int r0 = warp_m * 64 + mi * 16 + g;
#pragma unroll
        for (int ni = 0; ni < 4; ni++) {
            int n0 = warp_n * 32 + ni * 8 + tg * 2;
            float* a = acc[mi][ni];
            a[0] *= scale; a[1] *= scale; a[2] *= scale; a[3] *= scale;
            if (diag) {
                if (n0 > r0)     a[0] = NEG;
                if (n0 + 1 > r0) a[1] = NEG;
                if (n0 > r0 + 8)     a[2] = NEG;
                if (n0 + 1 > r0 + 8) a[3] = NEG;
            }
        }
    }

    // tile rowmax
    float mx[4][2];
#pragma unroll
    for (int mi = 0; mi < 4; mi++) {
        float m0 = -INFINITY, m1 = -INFINITY;
#pragma unroll
        for (int ni = 0; ni < 4; ni++) {
            m0 = fmaxf(m0, fmaxf(acc[mi][ni][0], acc[mi][ni][1]));
            m1 = fmaxf(m1, fmaxf(acc[mi][ni][2], acc[mi][ni][3]));
        }
        m0 = fmaxf(m0, __shfl_xor_sync(0xffffffffu, m0, 1));
        m0 = fmaxf(m0, __shfl_xor_sync(0xffffffffu, m0, 2));
        m1 = fmaxf(m1, __shfl_xor_sync(0xffffffffu, m1, 1));
        m1 = fmaxf(m1, __shfl_xor_sync(0xffffffffu, m1, 2));
        mx[mi][0] = m0; mx[mi][1] = m1;
    }
    if (tg == 0) {
#pragma unroll
        for (int mi = 0; mi < 4; mi++) {
            sred[warp_m * 64 + mi * 16 + g][warp_n] = mx[mi][0];
            sred[warp_m * 64 + mi * 16 + g + 8][warp_n] = mx[mi][1];
        }
    }
    __syncthreads();
    if (tid < 128) {
        sredm[tid] = fmaxf(fmaxf(sred[tid][0], sred[tid][1]),
                           fmaxf(sred[tid][2], sred[tid][3]));
    }
    __syncthreads();

    // E = exp(a - rowmax) in acc; accumulate sums; write E fp16
    __half* Eb = g_Eh + (size_t)bh * Tt * Tt;
#pragma unroll
    for (int mi = 0; mi < 4; mi++) {
        int r0 = warp_m * 64 + mi * 16 + g;
        float rm0 = sredm[r0];
        float rm1 = sredm[r0 + 8];
        float s0 = 0.f, s1 = 0.f;
#pragma unroll
        for (int ni = 0; ni < 4; ni++) {
            float* a = acc[mi][ni];
            a[0] = __expf(a[0] - rm0);
            a[1] = __expf(a[1] - rm0);
            a[2] = __expf(a[2] - rm1);
            a[3] = __expf(a[3] - rm1);
            s0 += a[0] + a[1];
            s1 += a[2] + a[3];
            int n0 = warp_n * 32 + ni * 8 + tg * 2;
            *(uint32_t*)(Eb + (size_t)(q0 + r0) * Tt + k0t + n0) = packh2(a[0], a[1]);
            *(uint32_t*)(Eb + (size_t)(q0 + r0 + 8) * Tt + k0t + n0) = packh2(a[2], a[3]);
        }
        s0 += __shfl_xor_sync(0xffffffffu, s0, 1);
        s0 += __shfl_xor_sync(0xffffffffu, s0, 2);
        s1 += __shfl_xor_sync(0xffffffffu, s1, 1);
        s1 += __shfl_xor_sync(0xffffffffu, s1, 2);
        mx[mi][0] = s0; mx[mi][1] = s1;
    }
    __syncthreads();
    if (tg == 0) {
#pragma unroll
        for (int mi = 0; mi < 4; mi++) {
            sred[warp_m * 64 + mi * 16 + g][warp_n] = mx[mi][0];
            sred[warp_m * 64 + mi * 16 + g + 8][warp_n] = mx[mi][1];
        }
    }
    __syncthreads();
    if (tid < 128) {
        float s4 = sred[tid][0] + sred[tid][1] + sred[tid][2] + sred[tid][3];
        size_t idx = (((size_t)bh * Tt + q0 + tid) * 16 + (k0t >> 7)) * 2;
        g_tilestats[idx] = sredm[tid];
        g_tilestats[idx + 1] = s4;
    }
}

// ---------------------------------------------------------------------------
// PV: prologue combines tile stats -> f[row][kt] = exp(mt-m)/l.
// Mainloop: cp.async E(fp16)+V(fp16), ldmatrix, scale A-frags by f (hmul2),
// mma; write final P = float(E)*f to attn_w from the same smem tile.
// ---------------------------------------------------------------------------
__global__ __launch_bounds__(256, 2) void pv_h(float* __restrict__ S)
{
    __shared__ __half Es[2][128 * 40];   // 20480 B
    __shared__ __half Vs[2][32 * 72];    //  9216 B
    __shared__ float fct[128][17];       //  8704 B

    const int qt = (NQT - 1) - blockIdx.x;   // heavy tiles first
    const int q0 = qt * 128;
    const int bh = blockIdx.y;
    const int b = bh / Hh, h = bh % Hh;
    const int tid = threadIdx.x, wid = tid >> 5, lane = tid & 31;
    const int g = lane >> 2, tg = lane & 3;
    const int warp_m = wid >> 1, warp_n = wid & 1;
    const int nkt = qt + 1;

    // prologue: per-row factors
    if (tid < 128) {
        const float* st = g_tilestats + ((size_t)bh * Tt + q0 + tid) * 32;
        float m = -INFINITY;
        for (int kt = 0; kt < nkt; kt++) m = fmaxf(m, st[kt * 2]);
        float l = 0.f;
        for (int kt = 0; kt < nkt; kt++) l += st[kt * 2 + 1] * __expf(st[kt * 2] - m);
        const float inv = 1.0f / l;
        for (int kt = 0; kt < nkt; kt++) fct[tid][kt] = __expf(st[kt * 2] - m) * inv;
    }

    float* Sb = S + (size_t)bh * Tt * Tt + (size_t)q0 * Tt;
    const __half* Ebg = g_Eh + (size_t)bh * Tt * Tt + (size_t)q0 * Tt;
    const __half* Vb = g_qkvh + (size_t)(b * Tt) * C3 + 2 * Cc + h * Dd;

    const uint32_t esb = (uint32_t)__cvta_generic_to_shared(Es);
    const uint32_t vsb = (uint32_t)__cvta_generic_to_shared(Vs);

    const int arow = (lane & 7) + ((lane >> 3) & 1) * 8;
    const int ahalf = lane >> 4;
    const int krow = (lane & 7) + ((lane >> 3) & 1) * 8;
    const int nhalf = (lane >> 4) * 8;

    auto issue = [&](int j) {
        const int s = j & 1, k0 = j * 32;
        const uint32_t eb = esb + (uint32_t)(s * 128 * 40 * 2);
#pragma unroll
        for (int i = 0; i < 2; i++) {
            int c = tid + i * 256, r = c >> 2, ch = c & 3;
            cpasync16(eb + r * 80 + ch * 16, Ebg + (size_t)r * Tt + k0 + ch * 8);
        }
        const uint32_t vb = vsb + (uint32_t)(s * 32 * 72 * 2);
        {
            int r = tid >> 3, ch = tid & 7;
            cpasync16(vb + r * 144 + ch * 16, Vb + (size_t)(k0 + r) * C3 + ch * 8);
        }
        asm volatile("cp.async.commit_group;");
    };

    const int nIter = nkt * 4;
    issue(0);

    float acc[2][4][4] = {};
    for (int j = 0; j < nIter; j++) {
        if (j + 1 < nIter) {
            issue(j + 1);
            asm volatile("cp.async.wait_group 1;");
        } else {
            asm volatile("cp.async.wait_group 0;");
        }
        __syncthreads();   // data ready; also covers fct on first iter

        const int s = j & 1;
        const int kt = j >> 2;
        const uint32_t ejb = esb + (uint32_t)(s * 128 * 40 * 2);
        const uint32_t vjb = vsb + (uint32_t)(s * 32 * 72 * 2);

        // per-fragment-row factors as half2
        uint32_t fh[2][2];
#pragma unroll
        for (int mi = 0; mi < 2; mi++) {
            int m = warp_m * 32 + mi * 16;
            __half2 t0 = __float2half2_rn(fct[m + g][kt]);
            __half2 t1 = __float2half2_rn(fct[m + g + 8][kt]);
            fh[mi][0] = *(uint32_t*)&t0;
            fh[mi][1] = *(uint32_t*)&t1;
        }

#pragma unroll
        for (int ks = 0; ks < 32; ks += 16) {
            uint32_t af[2][4], bf[2][4];
#pragma unroll
            for (int mi = 0; mi < 2; mi++) {
                ldsm4(af[mi], ejb + (warp_m * 32 + mi * 16 + arow) * 80 + (ks + ahalf * 8) * 2);
                af[mi][0] = hmul2u(af[mi][0], fh[mi][0]);
                af[mi][2] = hmul2u(af[mi][2], fh[mi][0]);
                af[mi][1] = hmul2u(af[mi][1], fh[mi][1]);
                af[mi][3] = hmul2u(af[mi][3], fh[mi][1]);
            }
#pragma unroll
            for (int np = 0; np < 2; np++)
                ldsm4t(bf[np], vjb + (ks + krow) * 144 + (warp_n * 32 + np * 16 + nhalf) * 2);
#pragma unroll
            for (int mi = 0; mi < 2; mi++)
#pragma unroll
                for (int np = 0; np < 2; np++) {
                    mma16h(acc[mi][np * 2 + 0], af[mi], &bf[np][0]);
                    mma16h(acc[mi][np * 2 + 1], af[mi], &bf[np][2]);
                }
        }

        // write P = float(E) * f to attn_w (final): row r, 16 cols per thread
        {
            const int r = tid >> 1, c0 = (tid & 1) * 16;
            const float f = fct[r][kt];
            const __half* Er = Es[s] + r * 40 + c0;
            float* dst = Sb + (size_t)r * Tt + j * 32 + c0;
#pragma unroll
            for (int q2 = 0; q2 < 2; q2++) {
                uint4 u = *(const uint4*)(Er + q2 * 8);
                float2 e0 = __half22float2(*(__half2*)&u.x);
                float2 e1 = __half22float2(*(__half2*)&u.y);
                float2 e2 = __half22float2(*(__half2*)&u.z);
                float2 e3 = __half22float2(*(__half2*)&u.w);
                float4 o0 = {e0.x * f, e0.y * f, e1.x * f, e1.y * f};
                float4 o1 = {e2.x * f, e2.y * f, e3.x * f, e3.y * f};
                *(float4*)(dst + q2 * 8) = o0;
                *(float4*)(dst + q2 * 8 + 4) = o1;
            }
        }
        __syncthreads();   // protect smem buffers before next issue overwrites
    }

#pragma unroll
    for (int mi = 0; mi < 2; mi++) {
#pragma unroll
        for (int ni = 0; ni < 4; ni++) {
            int q = q0 + warp_m * 32 + mi * 16 + g;
            int n = warp_n * 32 + ni * 8 + tg * 2;
            __half* dst0 = g_attnvh + (size_t)(b * Tt + q) * Cc + h * Dd + n;
            __half* dst1 = g_attnvh + (size_t)(b * Tt + q + 8) * Cc + h * Dd + n;
            *(uint32_t*)dst0 = packh2(acc[mi][ni][0], acc[mi][ni][1]);
            *(uint32_t*)dst1 = packh2(acc[mi][ni][2], acc[mi][ni][3]);
        }
    }
}

// ---------------------------------------------------------------------------
extern "C" void kernel_launch(void* const* d_in, const int* in_sizes, int n_in,
                              void* d_out, int out_size)
{
    const float* x     = (const float*)d_in[0];
    const float* w_qkv = (const float*)d_in[1];
    const float* b_qkv = (const float*)d_in[2];
    const float* w_o   = (const float*)d_in[3];
    const float* b_o   = (const float*)d_in[4];

    float* out   = (float*)d_out;
    float* attnw = out + (size_t)Mrows * Cc;   // [o | attn_w]

    __half *qkvh_ptr = nullptr, *attnvh_ptr = nullptr, *xh_ptr = nullptr;
    __half *wqkvTh_ptr = nullptr, *woTh_ptr = nullptr;
    cudaGetSymbolAddress((void**)&qkvh_ptr,   g_qkvh);
    cudaGetSymbolAddress((void**)&attnvh_ptr, g_attnvh);
    cudaGetSymbolAddress((void**)&xh_ptr,     g_xh);
    cudaGetSymbolAddress((void**)&wqkvTh_ptr, g_wqkvTh);
    cudaGetSymbolAddress((void**)&woTh_ptr,   g_woTh);

    const int gemm_smem   = 3 * 20480;          // 61440
    const int scores_smem = 2 * 128 * 72 * 2;   // 36864
    static bool attr_set = false;
    if (!attr_set) {
        cudaFuncSetAttribute(gemm_h<true>, cudaFuncAttributeMaxDynamicSharedMemorySize,
                             gemm_smem);
        cudaFuncSetAttribute(gemm_h<false>, cudaFuncAttributeMaxDynamicSharedMemorySize,
                             gemm_smem);
        cudaFuncSetAttribute(scores_h, cudaFuncAttributeMaxDynamicSharedMemorySize,
                             scores_smem);
        attr_set = true;
    }

    // 0) prep
    convert_x_h<<<(Mrows * Cc) / (256 * 8), 256>>>(x);
    {
        dim3 gt(C3 / 32, Cc / 32);
        transpose_h<<<gt, 256>>>(w_qkv, wqkvTh_ptr, C3, Cc);
    }
    {
        dim3 gt(Cc / 32, Cc / 32);
        transpose_h<<<gt, 256>>>(w_o, woTh_ptr, Cc, Cc);
    }
    // 1) QKV projection
    {
        dim3 grid(C3 / 128, Mrows / 128);
        gemm_h<true><<<grid, 256, gemm_smem>>>(xh_ptr, Cc, wqkvTh_ptr, Cc, b_qkv,
                                               qkvh_ptr, C3, Cc);
    }
    // 2) Scores -> E fp16 + tile stats (upper tiles -> final zeros in attn_w)
    {
        dim3 grid(Tt / 128, Tt / 128, BH);
        scores_h<<<grid, 256, scores_smem>>>(attnw);
    }
    // 3) P @ V (factors in prologue; writes final attn_w)
    {
        dim3 grid(NQT, BH);
        pv_h<<<grid, 256>>>(attnw);
    }
    // 4) Output projection
    {
        dim3 grid(Cc / 128, Mrows / 128);
        gemm_h<false><<<grid, 256, gemm_smem>>>(attnvh_ptr, Cc, woTh_ptr, Cc, b_o,
                                                out, Cc, Cc);
    }
}